// round 14
// baseline (speedup 1.0000x reference)
#include <cuda_runtime.h>
#include <math.h>

// Problem constants (fixed by the dataset)
#define cB 64
#define cN 499
#define cBN (cB*cN)          // 31936 tokens
#define NP 10001
#define NQ 2001
#define NA 11

#define BPC 4                // batches per cluster (16 clusters x 8 CTAs x BPC = 64)
#define BKK 16               // FFMA GEMM k-tile
#define TG_STAGE 18432       // tf32 GEMM: bytes per smem stage (128 rows x 36 floats)
#define TG_SMEM  73728       // 2 ops x 2 stages x 18432

// ------------------------- device scratch (no cudaMalloc allowed) -------------------------
__device__ __align__(16) float g_WhhT[256*1024];      // W_hh transposed: [k][gate]
__device__ __align__(16) float g_Wg1T[1024*256];      // W_g1^T  [n][o]
__device__ __align__(16) float g_WaT [256*512];       // W_affcat^T [o][i]
__device__ __align__(16) float g_Wg2T[256*1024];      // W_g2^T  [n][k]
__device__ __align__(16) float g_WcT [1024*512];      // (W_affcat @ W_g1)^T : [n][i]
__device__ __align__(16) float g_c1[1024];            // b_affcat @ W_g1
__device__ __align__(16) float g_Pp1[(size_t)NP*1024];   // emb_p @ Wc_p
__device__ __align__(16) float g_Pa1[NA*1024];           // emb_aff @ Wc_aff
__device__ __align__(16) float g_Pih_p[(size_t)NP*1024]; // emb_p @ W_ihT[0:256]
__device__ __align__(16) float g_Pih_q[(size_t)NQ*1024]; // emb_q @ W_ihT[256:512]
__device__ __align__(16) float g_Pih_r[2*1024];          // emb_r @ W_ihT[512:768]
__device__ __align__(16) float g_Ssp[NP*8];           // Pp1 . a_src1 (per head)
__device__ __align__(16) float g_Sdp[NP*8];           // Pp1 . a_dst1
__device__ __align__(16) float g_Ssa[NA*8];           // Pa1 . a_src1
__device__ __align__(16) float g_Sda[NA*8];           // Pa1 . a_dst1
__device__ __align__(16) float g_cs1[16];             // c1.a_src1 per head, then c1.a_dst1
__device__ __align__(16) float g_bsum[1024];          // b_ih + b_hh
__device__ __align__(16) float g_outp[NP];            // emb_p . W_out[512:768]
__device__ __align__(16) float g_outq[NQ];            // emb_q . W_out[256:512]
__device__ __align__(16) float g_big1[(size_t)cBN*1024];  // lstm_pre
__device__ __align__(16) float g_x1[(size_t)cBN*1024];
__device__ __align__(16) float g_h2[cBN*256];
__device__ __align__(16) float g_x2[cBN*256];
__device__ __align__(16) float g_es1[cBN*8];
__device__ __align__(16) float g_ed1[cBN*8];
__device__ __align__(16) float g_es2[cBN];
__device__ __align__(16) float g_ed2[cBN];
__device__ __align__(16) float g_hseq[cBN*256];
__device__ int g_off[cN+1];
__device__ int g_lst[4096];

// ------------------------- small helpers -------------------------
__device__ __forceinline__ unsigned smem_u32(const void* p) {
    unsigned a;
    asm("{ .reg .u64 t; cvta.to.shared.u64 t, %1; cvt.u32.u64 %0, t; }" : "=r"(a) : "l"(p));
    return a;
}
__device__ __forceinline__ void cpa16(unsigned dst, const void* src) {
    asm volatile("cp.async.ca.shared.global [%0], [%1], 16;" :: "r"(dst), "l"(src));
}
__device__ __forceinline__ void cpa16z(unsigned dst, const void* src, int n) {
    asm volatile("cp.async.ca.shared.global [%0], [%1], 16, %2;" :: "r"(dst), "l"(src), "r"(n));
}
#define CPA_COMMIT() asm volatile("cp.async.commit_group;" ::: "memory")
#define CLUSTER_SYNC() do { \
    asm volatile("barrier.cluster.arrive.aligned;" ::: "memory"); \
    asm volatile("barrier.cluster.wait.aligned;"   ::: "memory"); } while (0)

__device__ __forceinline__ void ldsm4(unsigned addr, unsigned* r) {
    asm volatile("ldmatrix.sync.aligned.m8n8.x4.shared.b16 {%0,%1,%2,%3}, [%4];"
                 : "=r"(r[0]), "=r"(r[1]), "=r"(r[2]), "=r"(r[3]) : "r"(addr));
}
__device__ __forceinline__ void ldsm2(unsigned addr, unsigned* r) {
    asm volatile("ldmatrix.sync.aligned.m8n8.x2.shared.b16 {%0,%1}, [%2];"
                 : "=r"(r[0]), "=r"(r[1]) : "r"(addr));
}
__device__ __forceinline__ unsigned f2tf(unsigned x) {
    unsigned y;
    asm("cvt.rna.tf32.f32 %0, %1;" : "=r"(y) : "r"(x));
    return y;
}
__device__ __forceinline__ void mma8(float* d, const unsigned* a, const unsigned* b) {
    asm volatile("mma.sync.aligned.m16n8k8.row.col.f32.tf32.tf32.f32 "
                 "{%0,%1,%2,%3}, {%4,%5,%6,%7}, {%8,%9}, {%0,%1,%2,%3};"
                 : "+f"(d[0]), "+f"(d[1]), "+f"(d[2]), "+f"(d[3])
                 : "r"(a[0]), "r"(a[1]), "r"(a[2]), "r"(a[3]), "r"(b[0]), "r"(b[1]));
}

// ------------------------- generic transpose -------------------------
__global__ void transpose_k(const float* __restrict__ in, float* __restrict__ out, int R, int C)
{
    int idx = blockIdx.x * blockDim.x + threadIdx.x;
    if (idx >= R * C) return;
    int c = idx / R;
    int r = idx - c * R;
    out[idx] = in[r * C + c];
}

// ------------------------- tf32 tensor-core GEMM core -------------------------
struct TGAcc { float a[4][4][4]; };

__device__ __forceinline__ void tgemm_main(const float* __restrict__ A, int lda,
                                           const float* __restrict__ Bn, int ldbn,
                                           int M, int K, int m0, int n0, TGAcc& AC)
{
    extern __shared__ float dynsm[];
    const unsigned smb = smem_u32(dynsm);
    const int tid = threadIdx.x, lane = tid & 31, wid = tid >> 5;
    const int wm = wid & 1, wn = wid >> 1;

    unsigned dOff[4];
    const float* sA[4];
    const float* sB[4];
    int vA[4];
#pragma unroll
    for (int i = 0; i < 4; i++) {
        int qd = tid + 256 * i;
        int row = qd >> 3, kq = qd & 7;
        dOff[i] = row * 144 + kq * 16;
        int ra = m0 + row;
        vA[i] = (ra < M) ? 16 : 0;
        sA[i] = A + (size_t)(vA[i] ? ra : 0) * lda + kq * 4;
        sB[i] = Bn + (size_t)(n0 + row) * ldbn + kq * 4;
    }

#pragma unroll
    for (int mt = 0; mt < 4; mt++)
#pragma unroll
        for (int nt = 0; nt < 4; nt++)
#pragma unroll
            for (int j = 0; j < 4; j++) AC.a[mt][nt][j] = 0.f;

#pragma unroll
    for (int i = 0; i < 4; i++) {
        cpa16z(smb + dOff[i], sA[i], vA[i]);
        cpa16z(smb + 2 * TG_STAGE + dOff[i], sB[i], 16);
    }
    CPA_COMMIT();

    const int aRowOff = wm * 64 + (lane & 7) + ((lane >> 3) & 1) * 8;
    const int aColB = (lane >> 4) * 16;
    const int bRowOff = wn * 32 + (lane & 7);
    const int bColB = ((lane >> 3) & 1) * 16;

    const int nst = K / 32;
    for (int st = 0; st < nst; st++) {
        const int buf = st & 1;
        if (st + 1 < nst) {
            const int k0 = (st + 1) * 32;
            const unsigned nb = (buf ^ 1) * TG_STAGE;
#pragma unroll
            for (int i = 0; i < 4; i++) {
                cpa16z(smb + nb + dOff[i], sA[i] + k0, vA[i]);
                cpa16z(smb + 2 * TG_STAGE + nb + dOff[i], sB[i] + k0, 16);
            }
            CPA_COMMIT();
            asm volatile("cp.async.wait_group 1;" ::: "memory");
        } else {
            asm volatile("cp.async.wait_group 0;" ::: "memory");
        }
        __syncthreads();
        const unsigned ab = smb + buf * TG_STAGE;
        const unsigned bb = smb + 2 * TG_STAGE + buf * TG_STAGE;
#pragma unroll
        for (int ks = 0; ks < 4; ks++) {
            unsigned af[4][4], bf[4][2];
#pragma unroll
            for (int mt = 0; mt < 4; mt++) {
                ldsm4(ab + (unsigned)((aRowOff + mt * 16) * 144 + aColB + ks * 32), af[mt]);
                af[mt][0] = f2tf(af[mt][0]); af[mt][1] = f2tf(af[mt][1]);
                af[mt][2] = f2tf(af[mt][2]); af[mt][3] = f2tf(af[mt][3]);
            }
#pragma unroll
            for (int nt = 0; nt < 4; nt++) {
                ldsm2(bb + (unsigned)((bRowOff + nt * 8) * 144 + bColB + ks * 32), bf[nt]);
                bf[nt][0] = f2tf(bf[nt][0]); bf[nt][1] = f2tf(bf[nt][1]);
            }
#pragma unroll
            for (int mt = 0; mt < 4; mt++)
#pragma unroll
                for (int nt = 0; nt < 4; nt++)
                    mma8(AC.a[mt][nt], af[mt], bf[nt]);
        }
        __syncthreads();
    }
}

// plain variant — 2 CTAs/SM
__global__ __launch_bounds__(256, 2) void tgemm(const float* __restrict__ A, int lda,
                                                const float* __restrict__ Bn, int ldbn,
                                                float* __restrict__ C, int ldc,
                                                int M, int N, int K, int accum)
{
    const int lane = threadIdx.x & 31, wid = threadIdx.x >> 5;
    const int wm = wid & 1, wn = wid >> 1;
    const int m0 = blockIdx.y * 128, n0 = blockIdx.x * 128;
    TGAcc AC;
    tgemm_main(A, lda, Bn, ldbn, M, K, m0, n0, AC);

    const int g = lane >> 2, c2 = (lane & 3) * 2;
#pragma unroll
    for (int mt = 0; mt < 4; mt++) {
        int r0 = m0 + wm * 64 + mt * 16 + g;
#pragma unroll
        for (int nt = 0; nt < 4; nt++) {
            int col = n0 + wn * 32 + nt * 8 + c2;
            if (r0 < M) {
                float2* pp = (float2*)(C + (size_t)r0 * ldc + col);
                float2 v = make_float2(AC.a[mt][nt][0], AC.a[mt][nt][1]);
                if (accum) { float2 o = *pp; v.x += o.x; v.y += o.y; }
                *pp = v;
            }
            if (r0 + 8 < M) {
                float2* pp = (float2*)(C + (size_t)(r0 + 8) * ldc + col);
                float2 v = make_float2(AC.a[mt][nt][2], AC.a[mt][nt][3]);
                if (accum) { float2 o = *pp; v.x += o.x; v.y += o.y; }
                *pp = v;
            }
        }
    }
}

// fused-epilogue variant: C = A@B + Tp[fp[m]] + Tq[fq[m]] + Tr[fr[m]] + bsum  (lstm pre)
__global__ __launch_bounds__(256, 2) void tgemm_pre(const float* __restrict__ A, int lda,
                                                    const float* __restrict__ Bn, int ldbn,
                                                    float* __restrict__ C, int ldc,
                                                    int M, int N, int K,
                                                    const int* __restrict__ fp,
                                                    const int* __restrict__ fq,
                                                    const int* __restrict__ fr,
                                                    const float* __restrict__ Tp,
                                                    const float* __restrict__ Tq,
                                                    const float* __restrict__ Tr,
                                                    const float* __restrict__ bsum)
{
    const int lane = threadIdx.x & 31, wid = threadIdx.x >> 5;
    const int wm = wid & 1, wn = wid >> 1;
    const int m0 = blockIdx.y * 128, n0 = blockIdx.x * 128;
    TGAcc AC;
    tgemm_main(A, lda, Bn, ldbn, M, K, m0, n0, AC);

    const int g = lane >> 2, c2 = (lane & 3) * 2;
#pragma unroll
    for (int mt = 0; mt < 4; mt++) {
        int r0 = m0 + wm * 64 + mt * 16 + g;
        bool ok0 = r0 < M, ok1 = (r0 + 8) < M;
        size_t p0 = 0, q0 = 0, rr0 = 0, p1 = 0, q1 = 0, rr1 = 0;
        if (ok0) { p0 = (size_t)fp[r0] * 1024; q0 = (size_t)fq[r0] * 1024; rr0 = (size_t)fr[r0] * 1024; }
        if (ok1) { p1 = (size_t)fp[r0+8] * 1024; q1 = (size_t)fq[r0+8] * 1024; rr1 = (size_t)fr[r0+8] * 1024; }
#pragma unroll
        for (int nt = 0; nt < 4; nt++) {
            int col = n0 + wn * 32 + nt * 8 + c2;
            float2 bs = *(const float2*)(bsum + col);
            if (ok0) {
                float2 tp = *(const float2*)(Tp + p0 + col);
                float2 tq = *(const float2*)(Tq + q0 + col);
                float2 tr = *(const float2*)(Tr + rr0 + col);
                float2 v = make_float2(AC.a[mt][nt][0] + tp.x + tq.x + tr.x + bs.x,
                                       AC.a[mt][nt][1] + tp.y + tq.y + tr.y + bs.y);
                *(float2*)(C + (size_t)r0 * ldc + col) = v;
            }
            if (ok1) {
                float2 tp = *(const float2*)(Tp + p1 + col);
                float2 tq = *(const float2*)(Tq + q1 + col);
                float2 tr = *(const float2*)(Tr + rr1 + col);
                float2 v = make_float2(AC.a[mt][nt][2] + tp.x + tq.x + tr.x + bs.x,
                                       AC.a[mt][nt][3] + tp.y + tq.y + tr.y + bs.y);
                *(float2*)(C + (size_t)(r0 + 8) * ldc + col) = v;
            }
        }
    }
}

// ------------------------- FFMA SGEMM (exact; Wc composition only) -------------------------
__global__ __launch_bounds__(256, 2) void sgemm_t(const float* __restrict__ A,
                                                  const float* __restrict__ Bm,
                                                  float* __restrict__ C,
                                                  int M, int K, int Nc, int accum)
{
    __shared__ float As[2][BKK][128];
    __shared__ float Bs[2][BKK][128];
    const int tid = threadIdx.x;
    const int m0 = blockIdx.x * 128, n0 = blockIdx.y * 128;
    const int tRow = (tid >> 4) * 8, tCol = (tid & 15) * 8;

    const int am0 = tid >> 2, ak = (tid & 3) * 4;
    const int am1 = am0 + 64;
    const int br0 = tid >> 5, bc = (tid & 31) * 4;
    const int br1 = br0 + 8;

    const bool v0 = (m0 + am0) < M, v1 = (m0 + am1) < M;
    const float* A0 = A + (size_t)(v0 ? m0 + am0 : 0) * K + ak;
    const float* A1 = A + (size_t)(v1 ? m0 + am1 : 0) * K + ak;
    const float* B0 = Bm + (size_t)br0 * Nc + n0 + bc;
    const float* B1 = Bm + (size_t)br1 * Nc + n0 + bc;

    unsigned sB00 = smem_u32(&Bs[0][br0][bc]), sB01 = smem_u32(&Bs[0][br1][bc]);
    unsigned sB10 = smem_u32(&Bs[1][br0][bc]), sB11 = smem_u32(&Bs[1][br1][bc]);

    float acc[8][8];
#pragma unroll
    for (int i = 0; i < 8; i++)
#pragma unroll
        for (int j = 0; j < 8; j++) acc[i][j] = 0.f;

    const float4 z4 = make_float4(0.f, 0.f, 0.f, 0.f);
    float4 a0 = v0 ? *(const float4*)A0 : z4;
    float4 a1 = v1 ? *(const float4*)A1 : z4;
    cpa16(sB00, B0);
    cpa16(sB01, B1);
    CPA_COMMIT();

    const int nt = K / BKK;
    for (int it = 0; it < nt; it++) {
        const int buf = it & 1;
        As[buf][ak + 0][am0] = a0.x; As[buf][ak + 1][am0] = a0.y;
        As[buf][ak + 2][am0] = a0.z; As[buf][ak + 3][am0] = a0.w;
        As[buf][ak + 0][am1] = a1.x; As[buf][ak + 1][am1] = a1.y;
        As[buf][ak + 2][am1] = a1.z; As[buf][ak + 3][am1] = a1.w;
        if (it + 1 < nt) {
            const int k0 = (it + 1) * BKK;
            a0 = v0 ? *(const float4*)(A0 + k0) : z4;
            a1 = v1 ? *(const float4*)(A1 + k0) : z4;
            cpa16(buf ? sB00 : sB10, B0 + (size_t)k0 * Nc);
            cpa16(buf ? sB01 : sB11, B1 + (size_t)k0 * Nc);
            CPA_COMMIT();
            asm volatile("cp.async.wait_group 1;" ::: "memory");
        } else {
            asm volatile("cp.async.wait_group 0;" ::: "memory");
        }
        __syncthreads();
#pragma unroll
        for (int kk = 0; kk < BKK; kk++) {
            float4 ra0 = *(const float4*)&As[buf][kk][tRow];
            float4 ra1 = *(const float4*)&As[buf][kk][tRow + 4];
            float4 rb0 = *(const float4*)&Bs[buf][kk][tCol];
            float4 rb1 = *(const float4*)&Bs[buf][kk][tCol + 4];
            float ra[8] = {ra0.x, ra0.y, ra0.z, ra0.w, ra1.x, ra1.y, ra1.z, ra1.w};
            float rb[8] = {rb0.x, rb0.y, rb0.z, rb0.w, rb1.x, rb1.y, rb1.z, rb1.w};
#pragma unroll
            for (int i = 0; i < 8; i++)
#pragma unroll
                for (int j = 0; j < 8; j++) acc[i][j] = fmaf(ra[i], rb[j], acc[i][j]);
        }
        __syncthreads();
    }

    for (int i = 0; i < 8; i++) {
        int m = m0 + tRow + i;
        if (m >= M) break;
        float* Crow = C + (size_t)m * Nc + n0 + tCol;
#pragma unroll
        for (int j = 0; j < 8; j += 4) {
            float4 v = make_float4(acc[i][j], acc[i][j+1], acc[i][j+2], acc[i][j+3]);
            if (accum) {
                float4 o = *(float4*)(Crow + j);
                v.x += o.x; v.y += o.y; v.z += o.z; v.w += o.w;
            }
            *(float4*)(Crow + j) = v;
        }
    }
}

// ------------------------- vec @ mat -------------------------
__global__ void vecmat_k(const float* __restrict__ v, const float* __restrict__ Wm,
                         float* __restrict__ out, int K, int Nc)
{
    int n = blockIdx.x * blockDim.x + threadIdx.x;
    if (n >= Nc) return;
    float acc = 0.f;
    for (int k = 0; k < K; k++) acc = fmaf(v[k], Wm[(size_t)k * Nc + n], acc);
    out[n] = acc;
}

// ------------------------- row dot (cols=256), float4 loads -------------------------
__global__ void rowdot_kernel(const float* __restrict__ emb, const float* __restrict__ w,
                              float* __restrict__ out, int rows)
{
    int gw = (blockIdx.x * blockDim.x + threadIdx.x) >> 5;
    int lane = threadIdx.x & 31;
    if (gw >= rows) return;
    const float* e = emb + (size_t)gw * 256;
    float acc = 0.f;
#pragma unroll
    for (int f0 = lane * 4; f0 < 256; f0 += 128) {
        float4 ev = *(const float4*)(e + f0);
        float4 wv = *(const float4*)(w + f0);
        acc = fmaf(ev.x, wv.x, acc); acc = fmaf(ev.y, wv.y, acc);
        acc = fmaf(ev.z, wv.z, acc); acc = fmaf(ev.w, wv.w, acc);
    }
    for (int o = 16; o; o >>= 1) acc += __shfl_xor_sync(0xffffffffu, acc, o);
    if (lane == 0) out[gw] = acc;
}

// ------------------------- per-table score tables (float4) -------------------------
__global__ void score_tab(const float* __restrict__ P, const float* __restrict__ a_s,
                          const float* __restrict__ a_d, float* __restrict__ Ss,
                          float* __restrict__ Sd)
{
    int row = blockIdx.x;
    int h = threadIdx.x >> 5;         // 8 warps = 8 heads
    int lane = threadIdx.x & 31;
    int f0 = h * 128 + lane * 4;
    float4 pv = *(const float4*)(P + (size_t)row * 1024 + f0);
    float4 as = *(const float4*)(a_s + f0);
    float4 ad = *(const float4*)(a_d + f0);
    float ss = pv.x * as.x + pv.y * as.y + pv.z * as.z + pv.w * as.w;
    float sd = pv.x * ad.x + pv.y * ad.y + pv.z * ad.z + pv.w * ad.w;
    for (int o = 16; o; o >>= 1) {
        ss += __shfl_xor_sync(0xffffffffu, ss, o);
        sd += __shfl_xor_sync(0xffffffffu, sd, o);
    }
    if (lane == 0) { Ss[row * 8 + h] = ss; Sd[row * 8 + h] = sd; }
}

// cs1[0..7] = c1.a_src per head, cs1[8..15] = c1.a_dst per head
__global__ void cvec_k(const float* __restrict__ c1, const float* __restrict__ a_s,
                       const float* __restrict__ a_d, float* __restrict__ cs)
{
    int w = threadIdx.x >> 5;         // 16 warps
    int lane = threadIdx.x & 31;
    int h = w & 7;
    const float* a = (w < 8) ? a_s : a_d;
    float acc = 0.f;
#pragma unroll
    for (int f = lane; f < 128; f += 32)
        acc = fmaf(c1[h * 128 + f], a[h * 128 + f], acc);
    for (int o = 16; o; o >>= 1) acc += __shfl_xor_sync(0xffffffffu, acc, o);
    if (lane == 0) cs[w] = acc;
}

__global__ void bsum_k(const float* __restrict__ a, const float* __restrict__ b,
                       float* __restrict__ o)
{
    int i = threadIdx.x;
    o[i] = a[i] + b[i];
}

// es1/ed1 gather
__global__ void scores_gather(const int* __restrict__ p, const int* __restrict__ aff,
                              const float* __restrict__ Ssp, const float* __restrict__ Ssa,
                              const float* __restrict__ Sdp, const float* __restrict__ Sda,
                              const float* __restrict__ cs, float* __restrict__ es,
                              float* __restrict__ ed)
{
    int idx = blockIdx.x * blockDim.x + threadIdx.x;
    if (idx >= cBN * 8) return;
    int bn = idx >> 3, h = idx & 7;
    int pv = p[bn], av = aff[bn];
    es[idx] = Ssp[pv * 8 + h] + Ssa[av * 8 + h] + cs[h];
    ed[idx] = Sdp[pv * 8 + h] + Sda[av * 8 + h] + cs[8 + h];
}

// ------------------------- deterministic CSR of incoming edges -------------------------
__global__ void csr_build(const int* __restrict__ dst, int E)
{
    __shared__ int cnt[cN];
    int tid = threadIdx.x;
    for (int n = tid; n < cN; n += blockDim.x) cnt[n] = 0;
    __syncthreads();
    for (int e = tid; e < E; e += blockDim.x) atomicAdd(&cnt[dst[e]], 1);
    __syncthreads();
    if (tid == 0) {
        int s = 0;
        for (int n = 0; n < cN; n++) { g_off[n] = s; s += cnt[n]; }
        g_off[cN] = s;
    }
    __syncthreads();
    for (int n = tid; n < cN; n += blockDim.x) cnt[n] = 0;
    __syncthreads();
    for (int e = tid; e < E; e += blockDim.x) {
        int d = dst[e];
        int pos = atomicAdd(&cnt[d], 1);
        g_lst[g_off[d] + pos] = e;
    }
    __syncthreads();
    for (int n = tid; n < cN; n += blockDim.x) {
        int o0 = g_off[n], o1 = g_off[n + 1];
        for (int i = o0 + 1; i < o1; i++) {
            int v = g_lst[i], j = i - 1;
            while (j >= o0 && g_lst[j] > v) { g_lst[j + 1] = g_lst[j]; j--; }
            g_lst[j + 1] = v;
        }
    }
}

// ------------------------- GAT1 fused aggregation: one WARP per destination node ----------
__global__ void gat1_agg_fused(const int* __restrict__ p, const int* __restrict__ aff,
                               const float* __restrict__ es, const float* __restrict__ ed,
                               const int* __restrict__ srcA,
                               const float* __restrict__ Pp1, const float* __restrict__ Pa1,
                               const float* __restrict__ c1, const float* __restrict__ bias,
                               float* __restrict__ out)
{
    int bn = (blockIdx.x * blockDim.x + threadIdx.x) >> 5;
    int lane = threadIdx.x & 31;
    if (bn >= cBN) return;
    int b = bn / cN, n = bn % cN;
    int o0 = g_off[n];
    int deg = g_off[n + 1] - o0;
    if (deg > 4) deg = 4;

    int ipj = 0, iaj = 0, bsj = 0;
    if (lane < deg) {
        int s = srcA[g_lst[o0 + lane]];
        bsj = b * cN + s;
        ipj = p[bsj];
        iaj = aff[bsj];
    }
    int ip[4], ia[4], bs[4];
#pragma unroll
    for (int j = 0; j < 4; j++) {
        ip[j] = __shfl_sync(0xffffffffu, ipj, j);
        ia[j] = __shfl_sync(0xffffffffu, iaj, j);
        bs[j] = __shfl_sync(0xffffffffu, bsj, j);
    }

    float w0 = 0.f, w1 = 0.f, w2 = 0.f, w3 = 0.f, winv = 1.f;
    if (lane < 8) {
        float edv = ed[bn * 8 + lane];
        float l[4];
        float mx = -1e30f;
        for (int j = 0; j < deg; j++) {
            float lv = es[bs[j] * 8 + lane] + edv;
            lv = lv > 0.f ? lv : 0.2f * lv;
            l[j] = lv;
            mx = fmaxf(mx, lv);
        }
        float sum = 0.f;
        for (int j = 0; j < deg; j++) { l[j] = expf(l[j] - mx); sum += l[j]; }
        w0 = l[0]; if (deg > 1) w1 = l[1]; if (deg > 2) w2 = l[2]; if (deg > 3) w3 = l[3];
        winv = 1.f / sum;
    }

    const size_t base = (size_t)bn * 1024;
#pragma unroll
    for (int c = 0; c < 8; c++) {
        float wj[4];
        wj[0] = __shfl_sync(0xffffffffu, w0, c);
        wj[1] = __shfl_sync(0xffffffffu, w1, c);
        wj[2] = __shfl_sync(0xffffffffu, w2, c);
        wj[3] = __shfl_sync(0xffffffffu, w3, c);
        float inv = __shfl_sync(0xffffffffu, winv, c);
        int fo = c * 128 + lane * 4;
        float4 acc = make_float4(0.f, 0.f, 0.f, 0.f);
        for (int j = 0; j < deg; j++) {
            float4 a = *(const float4*)(Pp1 + (size_t)ip[j] * 1024 + fo);
            float4 cc = *(const float4*)(Pa1 + (size_t)ia[j] * 1024 + fo);
            float ww = wj[j];
            acc.x = fmaf(ww, a.x + cc.x, acc.x);
            acc.y = fmaf(ww, a.y + cc.y, acc.y);
            acc.z = fmaf(ww, a.z + cc.z, acc.z);
            acc.w = fmaf(ww, a.w + cc.w, acc.w);
        }
        float4 cv = *(const float4*)(c1 + fo);
        float4 bi = *(const float4*)(bias + fo);
        float4 v;
        v.x = acc.x * inv + cv.x + bi.x;
        v.y = acc.y * inv + cv.y + bi.y;
        v.z = acc.z * inv + cv.z + bi.z;
        v.w = acc.w * inv + cv.w + bi.w;
        v.x = v.x > 0.f ? v.x : (expf(v.x) - 1.f);
        v.y = v.y > 0.f ? v.y : (expf(v.y) - 1.f);
        v.z = v.z > 0.f ? v.z : (expf(v.z) - 1.f);
        v.w = v.w > 0.f ? v.w : (expf(v.w) - 1.f);
        *(float4*)(out + base + fo) = v;
    }
}

// ------------------------- attention logits (GAT2), float4 -------------------------
__global__ void scores_kernel(const float* __restrict__ h, const float* __restrict__ a_s,
                              const float* __restrict__ a_d, float* __restrict__ es,
                              float* __restrict__ ed, int Hh, int Fo)
{
    int gw = (blockIdx.x * blockDim.x + threadIdx.x) >> 5;
    int lane = threadIdx.x & 31;
    if (gw >= cBN * Hh) return;
    int hh = gw % Hh;
    const float* hp = h + (size_t)gw * Fo;
    float ss = 0.f, sd = 0.f;
    for (int f0 = lane * 4; f0 < Fo; f0 += 128) {
        float4 hv = *(const float4*)(hp + f0);
        float4 as = *(const float4*)(a_s + hh * Fo + f0);
        float4 ad = *(const float4*)(a_d + hh * Fo + f0);
        ss = fmaf(hv.x, as.x, ss); ss = fmaf(hv.y, as.y, ss);
        ss = fmaf(hv.z, as.z, ss); ss = fmaf(hv.w, as.w, ss);
        sd = fmaf(hv.x, ad.x, sd); sd = fmaf(hv.y, ad.y, sd);
        sd = fmaf(hv.z, ad.z, sd); sd = fmaf(hv.w, ad.w, sd);
    }
    for (int o = 16; o; o >>= 1) {
        ss += __shfl_xor_sync(0xffffffffu, ss, o);
        sd += __shfl_xor_sync(0xffffffffu, sd, o);
    }
    if (lane == 0) { es[gw] = ss; ed[gw] = sd; }
}

// ------------------------- GAT2 aggregation, float4 -------------------------
__global__ void gat_agg(const float* __restrict__ h, const float* __restrict__ es,
                        const float* __restrict__ ed, const int* __restrict__ srcA,
                        const float* __restrict__ bias, float* __restrict__ out,
                        int Hh, int Fo, int elu)
{
    int gw = (blockIdx.x * blockDim.x + threadIdx.x) >> 5;
    int lane = threadIdx.x & 31;
    if (gw >= cBN * Hh) return;
    int hh = gw % Hh;
    int bn = gw / Hh;
    int b = bn / cN, n = bn % cN;
    int o0 = g_off[n];
    int deg = g_off[n + 1] - o0;
    if (deg > 4) deg = 4;
    int ssrc[4];
    float w[4];
    float edv = ed[(size_t)bn * Hh + hh];
    float mx = -1e30f;
    for (int j = 0; j < deg; j++) {
        int s = srcA[g_lst[o0 + j]];
        ssrc[j] = s;
        float l = es[((size_t)b * cN + s) * Hh + hh] + edv;
        l = l > 0.f ? l : 0.2f * l;
        w[j] = l;
        mx = fmaxf(mx, l);
    }
    float sum = 0.f;
    for (int j = 0; j < deg; j++) { w[j] = expf(w[j] - mx); sum += w[j]; }
    float inv = 1.f / sum;
    for (int f0 = lane * 4; f0 < Fo; f0 += 128) {
        float4 acc = make_float4(0.f, 0.f, 0.f, 0.f);
        for (int j = 0; j < deg; j++) {
            float4 hv = *(const float4*)(h + (((size_t)b * cN + ssrc[j]) * Hh + hh) * Fo + f0);
            float wj = w[j];
            acc.x = fmaf(wj, hv.x, acc.x); acc.y = fmaf(wj, hv.y, acc.y);
            acc.z = fmaf(wj, hv.z, acc.z); acc.w = fmaf(wj, hv.w, acc.w);
        }
        float4 bi = *(const float4*)(bias + hh * Fo + f0);
        float4 v;
        v.x = acc.x * inv + bi.x; v.y = acc.y * inv + bi.y;
        v.z = acc.z * inv + bi.z; v.w = acc.w * inv + bi.w;
        if (elu) {
            v.x = v.x > 0.f ? v.x : (expf(v.x) - 1.f);
            v.y = v.y > 0.f ? v.y : (expf(v.y) - 1.f);
            v.z = v.z > 0.f ? v.z : (expf(v.z) - 1.f);
            v.w = v.w > 0.f ? v.w : (expf(v.w) - 1.f);
        }
        *(float4*)(out + (size_t)gw * Fo + f0) = v;
    }
}

// ------------------------- cluster LSTM -------------------------
__global__ void __cluster_dims__(8, 1, 1) __launch_bounds__(256, 1)
lstm_cluster(const float* __restrict__ pre, const float* __restrict__ WhhT,
             float* __restrict__ hseq)
{
    __shared__ float hbuf[2][BPC][256];
    const int tid = threadIdx.x;
    const int hi = tid >> 3;
    const int kc = tid & 7;
    unsigned rank;
    asm("mov.u32 %0, %%cluster_ctarank;" : "=r"(rank));
    const int b0 = (blockIdx.x >> 3) * BPC;
    const int hg = (int)rank * 32 + hi;

    float w[4][32];
#pragma unroll
    for (int g = 0; g < 4; g++)
#pragma unroll
        for (int k = 0; k < 32; k++)
            w[g][k] = WhhT[(size_t)(kc * 32 + k) * 1024 + g * 256 + hg];

    for (int i = tid; i < 2 * BPC * 256; i += 256)
        ((float*)hbuf)[i] = 0.f;

    float cst = 0.f;
    const unsigned hb_base = smem_u32(hbuf);

    CLUSTER_SYNC();

    for (int t = 0; t < cN; t++) {
        const int pb = t & 1;
        float pg0 = 0.f, pg1 = 0.f, pg2 = 0.f, pg3 = 0.f;
        if (kc < BPC) {
            const float* pr = pre + ((size_t)((b0 + kc) * cN + t)) * 1024 + hg;
            pg0 = pr[0]; pg1 = pr[256]; pg2 = pr[512]; pg3 = pr[768];
        }

        float acc[4][BPC];
#pragma unroll
        for (int g = 0; g < 4; g++)
#pragma unroll
            for (int b = 0; b < BPC; b++) acc[g][b] = 0.f;

#pragma unroll
        for (int b = 0; b < BPC; b++) {
            const float* hp = &hbuf[pb][b][kc * 32];
#pragma unroll
            for (int k = 0; k < 32; k += 4) {
                float4 h4 = *(const float4*)(hp + k);
#pragma unroll
                for (int g = 0; g < 4; g++) {
                    acc[g][b] = fmaf(h4.x, w[g][k + 0], acc[g][b]);
                    acc[g][b] = fmaf(h4.y, w[g][k + 1], acc[g][b]);
                    acc[g][b] = fmaf(h4.z, w[g][k + 2], acc[g][b]);
                    acc[g][b] = fmaf(h4.w, w[g][k + 3], acc[g][b]);
                }
            }
        }

#pragma unroll
        for (int o = 1; o < 8; o <<= 1)
#pragma unroll
            for (int g = 0; g < 4; g++)
#pragma unroll
                for (int b = 0; b < BPC; b++)
                    acc[g][b] += __shfl_xor_sync(0xffffffffu, acc[g][b], o);

        if (kc < BPC) {
            const int b = kc;
            float iv = acc[0][b] + pg0;
            float fv = acc[1][b] + pg1;
            float gv = acc[2][b] + pg2;
            float ov = acc[3][b] + pg3;
            float ig = 1.f / (1.f + __expf(-iv));
            float fg = 1.f / (1.f + __expf(-fv));
            float og = 1.f / (1.f + __expf(-ov));
            cst = fg * cst + ig * tanhf(gv);
            float hval = og * tanhf(cst);
            hseq[((size_t)((b0 + b) * cN + t)) * 256 + hg] = hval;
            unsigned off = hb_base + (unsigned)((((1 - pb) * BPC + b) * 256 + hg) * 4);
#pragma unroll
            for (int peer = 0; peer < 8; peer++) {
                asm volatile(
                    "{ .reg .b32 ra; mapa.shared::cluster.u32 ra, %0, %1; "
                    "st.shared::cluster.f32 [ra], %2; }"
                    :: "r"(off), "r"(peer), "f"(hval) : "memory");
            }
        }
        CLUSTER_SYNC();
    }
}

// ------------------------- output head, float4 -------------------------
__global__ void out_kernel(const int* __restrict__ qn, const int* __restrict__ pn,
                           const float* __restrict__ Wout, const float* __restrict__ b_out,
                           const float* __restrict__ hseq, const float* __restrict__ outp,
                           const float* __restrict__ outq, float* __restrict__ y)
{
    int gw = (blockIdx.x * blockDim.x + threadIdx.x) >> 5;
    int lane = threadIdx.x & 31;
    if (gw >= cBN) return;
    const float* hp = hseq + (size_t)gw * 256;
    float acc = 0.f;
#pragma unroll
    for (int f0 = lane * 4; f0 < 256; f0 += 128) {
        float4 hv = *(const float4*)(hp + f0);
        float4 wv = *(const float4*)(Wout + f0);
        acc = fmaf(hv.x, wv.x, acc); acc = fmaf(hv.y, wv.y, acc);
        acc = fmaf(hv.z, wv.z, acc); acc = fmaf(hv.w, wv.w, acc);
    }
    for (int o = 16; o; o >>= 1) acc += __shfl_xor_sync(0xffffffffu, acc, o);
    if (lane == 0) {
        float v = acc + outq[qn[gw]] + outp[pn[gw]] + b_out[0];
        y[gw] = 1.f / (1.f + expf(-v));
    }
}

// ------------------------- host orchestration -------------------------
static inline dim3 tg(int M, int N) { return dim3(N / 128, (M + 127) / 128); }

extern "C" void kernel_launch(void* const* d_in, const int* in_sizes, int n_in,
                              void* d_out, int out_size)
{
    const int*   p       = (const int*)d_in[1];
    const int*   q       = (const int*)d_in[2];
    const int*   r       = (const int*)d_in[3];
    const int*   aff     = (const int*)d_in[4];
    const int*   q_next  = (const int*)d_in[5];
    const int*   p_next  = (const int*)d_in[6];
    const int*   src     = (const int*)d_in[7];
    const int*   dst     = (const int*)d_in[8];
    const float* emb_p   = (const float*)d_in[9];
    const float* emb_q   = (const float*)d_in[10];
    const float* emb_r   = (const float*)d_in[11];
    const float* emb_aff = (const float*)d_in[12];
    const float* W_affcat= (const float*)d_in[13];
    const float* b_affcat= (const float*)d_in[14];
    const float* W_g1    = (const float*)d_in[15];
    const float* a_src1  = (const float*)d_in[16];
    const float* a_dst1  = (const float*)d_in[17];
    const float* b_g1    = (const float*)d_in[18];
    const float* W_g2    = (const float*)d_in[19];
    const float* a_src2  = (const float*)d_in[20];
    const float* a_dst2  = (const float*)d_in[21];
    const float* b_g2    = (const float*)d_in[22];
    const float* W_ih    = (const float*)d_in[23];
    const float* W_hh    = (const float*)d_in[24];
    const float* b_ih    = (const float*)d_in[25];
    const float* b_hh    = (const float*)d_in[26];
    const float* W_out   = (const float*)d_in[27];
    const float* b_out   = (const float*)d_in[28];
    int E = in_sizes[7];

    float *WhhT, *Wg1T, *WaT, *Wg2T, *WcT, *c1, *Pp1, *Pa1, *Pih_p, *Pih_q, *Pih_r;
    float *Ssp, *Sdp, *Ssa, *Sda, *cs1, *bsum;
    float *big1, *x1, *h2, *x2, *es1, *ed1, *es2, *ed2, *hseq, *outp, *outq;
    cudaGetSymbolAddress((void**)&WhhT,  g_WhhT);
    cudaGetSymbolAddress((void**)&Wg1T,  g_Wg1T);
    cudaGetSymbolAddress((void**)&WaT,   g_WaT);
    cudaGetSymbolAddress((void**)&Wg2T,  g_Wg2T);
    cudaGetSymbolAddress((void**)&WcT,   g_WcT);
    cudaGetSymbolAddress((void**)&c1,    g_c1);
    cudaGetSymbolAddress((void**)&Pp1,   g_Pp1);
    cudaGetSymbolAddress((void**)&Pa1,   g_Pa1);
    cudaGetSymbolAddress((void**)&Pih_p, g_Pih_p);
    cudaGetSymbolAddress((void**)&Pih_q, g_Pih_q);
    cudaGetSymbolAddress((void**)&Pih_r, g_Pih_r);
    cudaGetSymbolAddress((void**)&Ssp,   g_Ssp);
    cudaGetSymbolAddress((void**)&Sdp,   g_Sdp);
    cudaGetSymbolAddress((void**)&Ssa,   g_Ssa);
    cudaGetSymbolAddress((void**)&Sda,   g_Sda);
    cudaGetSymbolAddress((void**)&cs1,   g_cs1);
    cudaGetSymbolAddress((void**)&bsum,  g_bsum);
    cudaGetSymbolAddress((void**)&big1,  g_big1);
    cudaGetSymbolAddress((void**)&x1,    g_x1);
    cudaGetSymbolAddress((void**)&h2,    g_h2);
    cudaGetSymbolAddress((void**)&x2,    g_x2);
    cudaGetSymbolAddress((void**)&es1,   g_es1);
    cudaGetSymbolAddress((void**)&ed1,   g_ed1);
    cudaGetSymbolAddress((void**)&es2,   g_es2);
    cudaGetSymbolAddress((void**)&ed2,   g_ed2);
    cudaGetSymbolAddress((void**)&hseq,  g_hseq);
    cudaGetSymbolAddress((void**)&outp,  g_outp);
    cudaGetSymbolAddress((void**)&outq,  g_outq);

    cudaFuncSetAttribute(tgemm, cudaFuncAttributeMaxDynamicSharedMemorySize, TG_SMEM);
    cudaFuncSetAttribute(tgemm_pre, cudaFuncAttributeMaxDynamicSharedMemorySize, TG_SMEM);

    // --- launches 1-3 (dependency-free), then LSTM PROBE at slot 4 (the ncu capture slot).
    // The probe reads stale-but-deterministic big1/WhhT; its hseq output is overwritten by
    // the real lstm_cluster below, so the final result is unchanged. Its cost ADDS to the
    // total: dur_delta vs R13 = t_lstm, and ncu profiles the LSTM directly.
    rowdot_kernel<<<(NP*32 + 255)/256, 256>>>(emb_p, W_out + 512, outp, NP);   // 1
    rowdot_kernel<<<(NQ*32 + 255)/256, 256>>>(emb_q, W_out + 256, outq, NQ);   // 2
    tgemm<<<tg(NP, 1024), 256, TG_SMEM>>>(emb_p, 256, W_ih,       1024, Pih_p, 1024, NP, 1024, 256, 0); // 3
    lstm_cluster<<<128, 256>>>(big1, WhhT, hseq);                              // 4 <-- PROBE
    tgemm<<<tg(NQ, 1024), 256, TG_SMEM>>>(emb_q, 256, W_ih + 256, 1024, Pih_q, 1024, NQ, 1024, 256, 0); // 5
    tgemm<<<tg(2,  1024), 256, TG_SMEM>>>(emb_r, 256, W_ih + 512, 1024, Pih_r, 1024, 2,  1024, 256, 0); // 6
    csr_build<<<1, 512>>>(dst, E);                                             // 7

    // --- weight preprocessing (small) ---
    transpose_k<<<(1024*256)/256, 256>>>(W_hh, WhhT, 1024, 256);
    transpose_k<<<(256*1024)/256, 256>>>(W_g1, Wg1T, 256, 1024);
    transpose_k<<<(512*256)/256,  256>>>(W_affcat, WaT, 512, 256);
    transpose_k<<<(1024*256)/256, 256>>>(W_g2, Wg2T, 1024, 256);

    sgemm_t<<<dim3(8, 4), 256>>>(Wg1T, WaT, WcT, 1024, 256, 512, 0);
    vecmat_k<<<4, 256>>>(b_affcat, W_g1, c1, 256, 1024);
    bsum_k<<<1, 1024>>>(b_ih, b_hh, bsum);

    // --- remaining per-table pre-projections (tf32 tensor cores) ---
    tgemm<<<tg(NP, 1024), 256, TG_SMEM>>>(emb_p,   256, WcT,       512, Pp1, 1024, NP, 1024, 256, 0);
    tgemm<<<tg(NA, 1024), 256, TG_SMEM>>>(emb_aff, 256, WcT + 256, 512, Pa1, 1024, NA, 1024, 256, 0);

    // per-table attention score tables
    score_tab<<<NP, 256>>>(Pp1, a_src1, a_dst1, Ssp, Sdp);
    score_tab<<<NA, 256>>>(Pa1, a_src1, a_dst1, Ssa, Sda);
    cvec_k<<<1, 512>>>(c1, a_src1, a_dst1, cs1);

    // --- GAT layer 1: logits + fused aggregation straight from tables ---
    scores_gather<<<(cBN*8 + 255)/256, 256>>>(p, aff, Ssp, Ssa, Sdp, Sda, cs1, es1, ed1);
    gat1_agg_fused<<<(cBN*32 + 255)/256, 256>>>(p, aff, es1, ed1, src, Pp1, Pa1, c1, b_g1, x1);

    // --- GAT layer 2 ---
    tgemm<<<tg(cBN, 256), 256, TG_SMEM>>>(x1, 1024, Wg2T, 1024, h2, 256, cBN, 256, 1024, 0);
    scores_kernel<<<(cBN*32)/256, 256>>>(h2, a_src2, a_dst2, es2, ed2, 1, 256);
    gat_agg<<<(cBN*32)/256, 256>>>(h2, es2, ed2, src, b_g2, x2, 1, 256, 0);

    // --- LSTM input: GEMM with fused gather-epilogue ---
    tgemm_pre<<<tg(cBN, 1024), 256, TG_SMEM>>>(x2, 256, W_ih + 768, 1024, big1, 1024,
                                               cBN, 1024, 256,
                                               p, q, r, Pih_p, Pih_q, Pih_r, bsum);

    // --- LSTM recurrence (real; overwrites probe's hseq) ---
    lstm_cluster<<<128, 256>>>(big1, WhhT, hseq);

    // --- output head ---
    out_kernel<<<(cBN*32)/256, 256>>>(q_next, p_next, W_out, b_out, hseq, outp, outq,
                                      (float*)d_out);
}

// round 15
// speedup vs baseline: 1.9602x; 1.9602x over previous
#include <cuda_runtime.h>
#include <math.h>

// Problem constants (fixed by the dataset)
#define cB 64
#define cN 499
#define cBN (cB*cN)          // 31936 tokens
#define NP 10001
#define NQ 2001
#define NA 11

#define BPC 4                // batches per cluster (16 clusters x 8 CTAs x BPC = 64)
#define BKK 16               // FFMA GEMM k-tile
#define TG_STAGE 18432       // tf32 GEMM: bytes per smem stage (128 rows x 36 floats)
#define TG_SMEM  73728       // 2 ops x 2 stages x 18432

// ------------------------- device scratch (no cudaMalloc allowed) -------------------------
__device__ __align__(16) float g_WhhT[256*1024];      // W_hh transposed: [k][gate]
__device__ __align__(16) float g_Wg1T[1024*256];      // W_g1^T  [n][o]
__device__ __align__(16) float g_WaT [256*512];       // W_affcat^T [o][i]
__device__ __align__(16) float g_Wg2T[256*1024];      // W_g2^T  [n][k]
__device__ __align__(16) float g_WcT [1024*512];      // (W_affcat @ W_g1)^T : [n][i]
__device__ __align__(16) float g_c1[1024];            // b_affcat @ W_g1
__device__ __align__(16) float g_Pp1[(size_t)NP*1024];   // emb_p @ Wc_p
__device__ __align__(16) float g_Pa1[NA*1024];           // emb_aff @ Wc_aff
__device__ __align__(16) float g_Pih_p[(size_t)NP*1024]; // emb_p @ W_ihT[0:256]
__device__ __align__(16) float g_Pih_q[(size_t)NQ*1024]; // emb_q @ W_ihT[256:512]
__device__ __align__(16) float g_Pih_r[2*1024];          // emb_r @ W_ihT[512:768]
__device__ __align__(16) float g_Ssp[NP*8];           // Pp1 . a_src1 (per head)
__device__ __align__(16) float g_Sdp[NP*8];           // Pp1 . a_dst1
__device__ __align__(16) float g_Ssa[NA*8];           // Pa1 . a_src1
__device__ __align__(16) float g_Sda[NA*8];           // Pa1 . a_dst1
__device__ __align__(16) float g_cs1[16];             // c1.a_src1 per head, then c1.a_dst1
__device__ __align__(16) float g_bsum[1024];          // b_ih + b_hh
__device__ __align__(16) float g_outp[NP];            // emb_p . W_out[512:768]
__device__ __align__(16) float g_outq[NQ];            // emb_q . W_out[256:512]
__device__ __align__(16) float g_big1[(size_t)cBN*1024];  // lstm_pre
__device__ __align__(16) float g_x1[(size_t)cBN*1024];
__device__ __align__(16) float g_h2[cBN*256];
__device__ __align__(16) float g_x2[cBN*256];
__device__ __align__(16) float g_es1[cBN*8];
__device__ __align__(16) float g_ed1[cBN*8];
__device__ __align__(16) float g_es2[cBN];
__device__ __align__(16) float g_ed2[cBN];
__device__ __align__(16) float g_hseq[cBN*256];
__device__ int g_off[cN+1];
__device__ int g_lst[4096];

// ------------------------- small helpers -------------------------
__device__ __forceinline__ unsigned smem_u32(const void* p) {
    unsigned a;
    asm("{ .reg .u64 t; cvta.to.shared.u64 t, %1; cvt.u32.u64 %0, t; }" : "=r"(a) : "l"(p));
    return a;
}
__device__ __forceinline__ void cpa16(unsigned dst, const void* src) {
    asm volatile("cp.async.ca.shared.global [%0], [%1], 16;" :: "r"(dst), "l"(src));
}
__device__ __forceinline__ void cpa16z(unsigned dst, const void* src, int n) {
    asm volatile("cp.async.ca.shared.global [%0], [%1], 16, %2;" :: "r"(dst), "l"(src), "r"(n));
}
#define CPA_COMMIT() asm volatile("cp.async.commit_group;" ::: "memory")
#define CLUSTER_SYNC() do { \
    asm volatile("barrier.cluster.arrive.aligned;" ::: "memory"); \
    asm volatile("barrier.cluster.wait.aligned;"   ::: "memory"); } while (0)

__device__ __forceinline__ void ldsm4(unsigned addr, unsigned* r) {
    asm volatile("ldmatrix.sync.aligned.m8n8.x4.shared.b16 {%0,%1,%2,%3}, [%4];"
                 : "=r"(r[0]), "=r"(r[1]), "=r"(r[2]), "=r"(r[3]) : "r"(addr));
}
__device__ __forceinline__ void ldsm2(unsigned addr, unsigned* r) {
    asm volatile("ldmatrix.sync.aligned.m8n8.x2.shared.b16 {%0,%1}, [%2];"
                 : "=r"(r[0]), "=r"(r[1]) : "r"(addr));
}
__device__ __forceinline__ unsigned f2tf(unsigned x) {
    unsigned y;
    asm("cvt.rna.tf32.f32 %0, %1;" : "=r"(y) : "r"(x));
    return y;
}
__device__ __forceinline__ void mma8(float* d, const unsigned* a, const unsigned* b) {
    asm volatile("mma.sync.aligned.m16n8k8.row.col.f32.tf32.tf32.f32 "
                 "{%0,%1,%2,%3}, {%4,%5,%6,%7}, {%8,%9}, {%0,%1,%2,%3};"
                 : "+f"(d[0]), "+f"(d[1]), "+f"(d[2]), "+f"(d[3])
                 : "r"(a[0]), "r"(a[1]), "r"(a[2]), "r"(a[3]), "r"(b[0]), "r"(b[1]));
}

// ------------------------- generic transpose -------------------------
__global__ void transpose_k(const float* __restrict__ in, float* __restrict__ out, int R, int C)
{
    int idx = blockIdx.x * blockDim.x + threadIdx.x;
    if (idx >= R * C) return;
    int c = idx / R;
    int r = idx - c * R;
    out[idx] = in[r * C + c];
}

// ------------------------- tf32 tensor-core GEMM core -------------------------
struct TGAcc { float a[4][4][4]; };

__device__ __forceinline__ void tgemm_main(const float* __restrict__ A, int lda,
                                           const float* __restrict__ Bn, int ldbn,
                                           int M, int K, int m0, int n0, TGAcc& AC)
{
    extern __shared__ float dynsm[];
    const unsigned smb = smem_u32(dynsm);
    const int tid = threadIdx.x, lane = tid & 31, wid = tid >> 5;
    const int wm = wid & 1, wn = wid >> 1;

    unsigned dOff[4];
    const float* sA[4];
    const float* sB[4];
    int vA[4];
#pragma unroll
    for (int i = 0; i < 4; i++) {
        int qd = tid + 256 * i;
        int row = qd >> 3, kq = qd & 7;
        dOff[i] = row * 144 + kq * 16;
        int ra = m0 + row;
        vA[i] = (ra < M) ? 16 : 0;
        sA[i] = A + (size_t)(vA[i] ? ra : 0) * lda + kq * 4;
        sB[i] = Bn + (size_t)(n0 + row) * ldbn + kq * 4;
    }

#pragma unroll
    for (int mt = 0; mt < 4; mt++)
#pragma unroll
        for (int nt = 0; nt < 4; nt++)
#pragma unroll
            for (int j = 0; j < 4; j++) AC.a[mt][nt][j] = 0.f;

#pragma unroll
    for (int i = 0; i < 4; i++) {
        cpa16z(smb + dOff[i], sA[i], vA[i]);
        cpa16z(smb + 2 * TG_STAGE + dOff[i], sB[i], 16);
    }
    CPA_COMMIT();

    const int aRowOff = wm * 64 + (lane & 7) + ((lane >> 3) & 1) * 8;
    const int aColB = (lane >> 4) * 16;
    const int bRowOff = wn * 32 + (lane & 7);
    const int bColB = ((lane >> 3) & 1) * 16;

    const int nst = K / 32;
    for (int st = 0; st < nst; st++) {
        const int buf = st & 1;
        if (st + 1 < nst) {
            const int k0 = (st + 1) * 32;
            const unsigned nb = (buf ^ 1) * TG_STAGE;
#pragma unroll
            for (int i = 0; i < 4; i++) {
                cpa16z(smb + nb + dOff[i], sA[i] + k0, vA[i]);
                cpa16z(smb + 2 * TG_STAGE + nb + dOff[i], sB[i] + k0, 16);
            }
            CPA_COMMIT();
            asm volatile("cp.async.wait_group 1;" ::: "memory");
        } else {
            asm volatile("cp.async.wait_group 0;" ::: "memory");
        }
        __syncthreads();
        const unsigned ab = smb + buf * TG_STAGE;
        const unsigned bb = smb + 2 * TG_STAGE + buf * TG_STAGE;
#pragma unroll
        for (int ks = 0; ks < 4; ks++) {
            unsigned af[4][4], bf[4][2];
#pragma unroll
            for (int mt = 0; mt < 4; mt++) {
                ldsm4(ab + (unsigned)((aRowOff + mt * 16) * 144 + aColB + ks * 32), af[mt]);
                af[mt][0] = f2tf(af[mt][0]); af[mt][1] = f2tf(af[mt][1]);
                af[mt][2] = f2tf(af[mt][2]); af[mt][3] = f2tf(af[mt][3]);
            }
#pragma unroll
            for (int nt = 0; nt < 4; nt++) {
                ldsm2(bb + (unsigned)((bRowOff + nt * 8) * 144 + bColB + ks * 32), bf[nt]);
                bf[nt][0] = f2tf(bf[nt][0]); bf[nt][1] = f2tf(bf[nt][1]);
            }
#pragma unroll
            for (int mt = 0; mt < 4; mt++)
#pragma unroll
                for (int nt = 0; nt < 4; nt++)
                    mma8(AC.a[mt][nt], af[mt], bf[nt]);
        }
        __syncthreads();
    }
}

// plain variant — 2 CTAs/SM
__global__ __launch_bounds__(256, 2) void tgemm(const float* __restrict__ A, int lda,
                                                const float* __restrict__ Bn, int ldbn,
                                                float* __restrict__ C, int ldc,
                                                int M, int N, int K, int accum)
{
    const int lane = threadIdx.x & 31, wid = threadIdx.x >> 5;
    const int wm = wid & 1, wn = wid >> 1;
    const int m0 = blockIdx.y * 128, n0 = blockIdx.x * 128;
    TGAcc AC;
    tgemm_main(A, lda, Bn, ldbn, M, K, m0, n0, AC);

    const int g = lane >> 2, c2 = (lane & 3) * 2;
#pragma unroll
    for (int mt = 0; mt < 4; mt++) {
        int r0 = m0 + wm * 64 + mt * 16 + g;
#pragma unroll
        for (int nt = 0; nt < 4; nt++) {
            int col = n0 + wn * 32 + nt * 8 + c2;
            if (r0 < M) {
                float2* pp = (float2*)(C + (size_t)r0 * ldc + col);
                float2 v = make_float2(AC.a[mt][nt][0], AC.a[mt][nt][1]);
                if (accum) { float2 o = *pp; v.x += o.x; v.y += o.y; }
                *pp = v;
            }
            if (r0 + 8 < M) {
                float2* pp = (float2*)(C + (size_t)(r0 + 8) * ldc + col);
                float2 v = make_float2(AC.a[mt][nt][2], AC.a[mt][nt][3]);
                if (accum) { float2 o = *pp; v.x += o.x; v.y += o.y; }
                *pp = v;
            }
        }
    }
}

// fused-epilogue variant: C = A@B + Tp[fp[m]] + Tq[fq[m]] + Tr[fr[m]] + bsum  (lstm pre)
__global__ __launch_bounds__(256, 2) void tgemm_pre(const float* __restrict__ A, int lda,
                                                    const float* __restrict__ Bn, int ldbn,
                                                    float* __restrict__ C, int ldc,
                                                    int M, int N, int K,
                                                    const int* __restrict__ fp,
                                                    const int* __restrict__ fq,
                                                    const int* __restrict__ fr,
                                                    const float* __restrict__ Tp,
                                                    const float* __restrict__ Tq,
                                                    const float* __restrict__ Tr,
                                                    const float* __restrict__ bsum)
{
    const int lane = threadIdx.x & 31, wid = threadIdx.x >> 5;
    const int wm = wid & 1, wn = wid >> 1;
    const int m0 = blockIdx.y * 128, n0 = blockIdx.x * 128;
    TGAcc AC;
    tgemm_main(A, lda, Bn, ldbn, M, K, m0, n0, AC);

    const int g = lane >> 2, c2 = (lane & 3) * 2;
#pragma unroll
    for (int mt = 0; mt < 4; mt++) {
        int r0 = m0 + wm * 64 + mt * 16 + g;
        bool ok0 = r0 < M, ok1 = (r0 + 8) < M;
        size_t p0 = 0, q0 = 0, rr0 = 0, p1 = 0, q1 = 0, rr1 = 0;
        if (ok0) { p0 = (size_t)fp[r0] * 1024; q0 = (size_t)fq[r0] * 1024; rr0 = (size_t)fr[r0] * 1024; }
        if (ok1) { p1 = (size_t)fp[r0+8] * 1024; q1 = (size_t)fq[r0+8] * 1024; rr1 = (size_t)fr[r0+8] * 1024; }
#pragma unroll
        for (int nt = 0; nt < 4; nt++) {
            int col = n0 + wn * 32 + nt * 8 + c2;
            float2 bs = *(const float2*)(bsum + col);
            if (ok0) {
                float2 tp = *(const float2*)(Tp + p0 + col);
                float2 tq = *(const float2*)(Tq + q0 + col);
                float2 tr = *(const float2*)(Tr + rr0 + col);
                float2 v = make_float2(AC.a[mt][nt][0] + tp.x + tq.x + tr.x + bs.x,
                                       AC.a[mt][nt][1] + tp.y + tq.y + tr.y + bs.y);
                *(float2*)(C + (size_t)r0 * ldc + col) = v;
            }
            if (ok1) {
                float2 tp = *(const float2*)(Tp + p1 + col);
                float2 tq = *(const float2*)(Tq + q1 + col);
                float2 tr = *(const float2*)(Tr + rr1 + col);
                float2 v = make_float2(AC.a[mt][nt][2] + tp.x + tq.x + tr.x + bs.x,
                                       AC.a[mt][nt][3] + tp.y + tq.y + tr.y + bs.y);
                *(float2*)(C + (size_t)(r0 + 8) * ldc + col) = v;
            }
        }
    }
}

// ------------------------- FFMA SGEMM (exact; Wc composition only) -------------------------
__global__ __launch_bounds__(256, 2) void sgemm_t(const float* __restrict__ A,
                                                  const float* __restrict__ Bm,
                                                  float* __restrict__ C,
                                                  int M, int K, int Nc, int accum)
{
    __shared__ float As[2][BKK][128];
    __shared__ float Bs[2][BKK][128];
    const int tid = threadIdx.x;
    const int m0 = blockIdx.x * 128, n0 = blockIdx.y * 128;
    const int tRow = (tid >> 4) * 8, tCol = (tid & 15) * 8;

    const int am0 = tid >> 2, ak = (tid & 3) * 4;
    const int am1 = am0 + 64;
    const int br0 = tid >> 5, bc = (tid & 31) * 4;
    const int br1 = br0 + 8;

    const bool v0 = (m0 + am0) < M, v1 = (m0 + am1) < M;
    const float* A0 = A + (size_t)(v0 ? m0 + am0 : 0) * K + ak;
    const float* A1 = A + (size_t)(v1 ? m0 + am1 : 0) * K + ak;
    const float* B0 = Bm + (size_t)br0 * Nc + n0 + bc;
    const float* B1 = Bm + (size_t)br1 * Nc + n0 + bc;

    unsigned sB00 = smem_u32(&Bs[0][br0][bc]), sB01 = smem_u32(&Bs[0][br1][bc]);
    unsigned sB10 = smem_u32(&Bs[1][br0][bc]), sB11 = smem_u32(&Bs[1][br1][bc]);

    float acc[8][8];
#pragma unroll
    for (int i = 0; i < 8; i++)
#pragma unroll
        for (int j = 0; j < 8; j++) acc[i][j] = 0.f;

    const float4 z4 = make_float4(0.f, 0.f, 0.f, 0.f);
    float4 a0 = v0 ? *(const float4*)A0 : z4;
    float4 a1 = v1 ? *(const float4*)A1 : z4;
    cpa16(sB00, B0);
    cpa16(sB01, B1);
    CPA_COMMIT();

    const int nt = K / BKK;
    for (int it = 0; it < nt; it++) {
        const int buf = it & 1;
        As[buf][ak + 0][am0] = a0.x; As[buf][ak + 1][am0] = a0.y;
        As[buf][ak + 2][am0] = a0.z; As[buf][ak + 3][am0] = a0.w;
        As[buf][ak + 0][am1] = a1.x; As[buf][ak + 1][am1] = a1.y;
        As[buf][ak + 2][am1] = a1.z; As[buf][ak + 3][am1] = a1.w;
        if (it + 1 < nt) {
            const int k0 = (it + 1) * BKK;
            a0 = v0 ? *(const float4*)(A0 + k0) : z4;
            a1 = v1 ? *(const float4*)(A1 + k0) : z4;
            cpa16(buf ? sB00 : sB10, B0 + (size_t)k0 * Nc);
            cpa16(buf ? sB01 : sB11, B1 + (size_t)k0 * Nc);
            CPA_COMMIT();
            asm volatile("cp.async.wait_group 1;" ::: "memory");
        } else {
            asm volatile("cp.async.wait_group 0;" ::: "memory");
        }
        __syncthreads();
#pragma unroll
        for (int kk = 0; kk < BKK; kk++) {
            float4 ra0 = *(const float4*)&As[buf][kk][tRow];
            float4 ra1 = *(const float4*)&As[buf][kk][tRow + 4];
            float4 rb0 = *(const float4*)&Bs[buf][kk][tCol];
            float4 rb1 = *(const float4*)&Bs[buf][kk][tCol + 4];
            float ra[8] = {ra0.x, ra0.y, ra0.z, ra0.w, ra1.x, ra1.y, ra1.z, ra1.w};
            float rb[8] = {rb0.x, rb0.y, rb0.z, rb0.w, rb1.x, rb1.y, rb1.z, rb1.w};
#pragma unroll
            for (int i = 0; i < 8; i++)
#pragma unroll
                for (int j = 0; j < 8; j++) acc[i][j] = fmaf(ra[i], rb[j], acc[i][j]);
        }
        __syncthreads();
    }

    for (int i = 0; i < 8; i++) {
        int m = m0 + tRow + i;
        if (m >= M) break;
        float* Crow = C + (size_t)m * Nc + n0 + tCol;
#pragma unroll
        for (int j = 0; j < 8; j += 4) {
            float4 v = make_float4(acc[i][j], acc[i][j+1], acc[i][j+2], acc[i][j+3]);
            if (accum) {
                float4 o = *(float4*)(Crow + j);
                v.x += o.x; v.y += o.y; v.z += o.z; v.w += o.w;
            }
            *(float4*)(Crow + j) = v;
        }
    }
}

// ------------------------- vec @ mat -------------------------
__global__ void vecmat_k(const float* __restrict__ v, const float* __restrict__ Wm,
                         float* __restrict__ out, int K, int Nc)
{
    int n = blockIdx.x * blockDim.x + threadIdx.x;
    if (n >= Nc) return;
    float acc = 0.f;
    for (int k = 0; k < K; k++) acc = fmaf(v[k], Wm[(size_t)k * Nc + n], acc);
    out[n] = acc;
}

// ------------------------- row dot (cols=256), float4 loads -------------------------
__global__ void rowdot_kernel(const float* __restrict__ emb, const float* __restrict__ w,
                              float* __restrict__ out, int rows)
{
    int gw = (blockIdx.x * blockDim.x + threadIdx.x) >> 5;
    int lane = threadIdx.x & 31;
    if (gw >= rows) return;
    const float* e = emb + (size_t)gw * 256;
    float acc = 0.f;
#pragma unroll
    for (int f0 = lane * 4; f0 < 256; f0 += 128) {
        float4 ev = *(const float4*)(e + f0);
        float4 wv = *(const float4*)(w + f0);
        acc = fmaf(ev.x, wv.x, acc); acc = fmaf(ev.y, wv.y, acc);
        acc = fmaf(ev.z, wv.z, acc); acc = fmaf(ev.w, wv.w, acc);
    }
    for (int o = 16; o; o >>= 1) acc += __shfl_xor_sync(0xffffffffu, acc, o);
    if (lane == 0) out[gw] = acc;
}

// ------------------------- per-table score tables (float4) -------------------------
__global__ void score_tab(const float* __restrict__ P, const float* __restrict__ a_s,
                          const float* __restrict__ a_d, float* __restrict__ Ss,
                          float* __restrict__ Sd)
{
    int row = blockIdx.x;
    int h = threadIdx.x >> 5;         // 8 warps = 8 heads
    int lane = threadIdx.x & 31;
    int f0 = h * 128 + lane * 4;
    float4 pv = *(const float4*)(P + (size_t)row * 1024 + f0);
    float4 as = *(const float4*)(a_s + f0);
    float4 ad = *(const float4*)(a_d + f0);
    float ss = pv.x * as.x + pv.y * as.y + pv.z * as.z + pv.w * as.w;
    float sd = pv.x * ad.x + pv.y * ad.y + pv.z * ad.z + pv.w * ad.w;
    for (int o = 16; o; o >>= 1) {
        ss += __shfl_xor_sync(0xffffffffu, ss, o);
        sd += __shfl_xor_sync(0xffffffffu, sd, o);
    }
    if (lane == 0) { Ss[row * 8 + h] = ss; Sd[row * 8 + h] = sd; }
}

// cs1[0..7] = c1.a_src per head, cs1[8..15] = c1.a_dst per head
__global__ void cvec_k(const float* __restrict__ c1, const float* __restrict__ a_s,
                       const float* __restrict__ a_d, float* __restrict__ cs)
{
    int w = threadIdx.x >> 5;         // 16 warps
    int lane = threadIdx.x & 31;
    int h = w & 7;
    const float* a = (w < 8) ? a_s : a_d;
    float acc = 0.f;
#pragma unroll
    for (int f = lane; f < 128; f += 32)
        acc = fmaf(c1[h * 128 + f], a[h * 128 + f], acc);
    for (int o = 16; o; o >>= 1) acc += __shfl_xor_sync(0xffffffffu, acc, o);
    if (lane == 0) cs[w] = acc;
}

__global__ void bsum_k(const float* __restrict__ a, const float* __restrict__ b,
                       float* __restrict__ o)
{
    int i = threadIdx.x;
    o[i] = a[i] + b[i];
}

// es1/ed1 gather
__global__ void scores_gather(const int* __restrict__ p, const int* __restrict__ aff,
                              const float* __restrict__ Ssp, const float* __restrict__ Ssa,
                              const float* __restrict__ Sdp, const float* __restrict__ Sda,
                              const float* __restrict__ cs, float* __restrict__ es,
                              float* __restrict__ ed)
{
    int idx = blockIdx.x * blockDim.x + threadIdx.x;
    if (idx >= cBN * 8) return;
    int bn = idx >> 3, h = idx & 7;
    int pv = p[bn], av = aff[bn];
    es[idx] = Ssp[pv * 8 + h] + Ssa[av * 8 + h] + cs[h];
    ed[idx] = Sdp[pv * 8 + h] + Sda[av * 8 + h] + cs[8 + h];
}

// ------------------------- deterministic CSR of incoming edges -------------------------
__global__ void csr_build(const int* __restrict__ dst, int E)
{
    __shared__ int cnt[cN];
    int tid = threadIdx.x;
    for (int n = tid; n < cN; n += blockDim.x) cnt[n] = 0;
    __syncthreads();
    for (int e = tid; e < E; e += blockDim.x) atomicAdd(&cnt[dst[e]], 1);
    __syncthreads();
    if (tid == 0) {
        int s = 0;
        for (int n = 0; n < cN; n++) { g_off[n] = s; s += cnt[n]; }
        g_off[cN] = s;
    }
    __syncthreads();
    for (int n = tid; n < cN; n += blockDim.x) cnt[n] = 0;
    __syncthreads();
    for (int e = tid; e < E; e += blockDim.x) {
        int d = dst[e];
        int pos = atomicAdd(&cnt[d], 1);
        g_lst[g_off[d] + pos] = e;
    }
    __syncthreads();
    for (int n = tid; n < cN; n += blockDim.x) {
        int o0 = g_off[n], o1 = g_off[n + 1];
        for (int i = o0 + 1; i < o1; i++) {
            int v = g_lst[i], j = i - 1;
            while (j >= o0 && g_lst[j] > v) { g_lst[j + 1] = g_lst[j]; j--; }
            g_lst[j + 1] = v;
        }
    }
}

// ------------------------- GAT1 fused aggregation: one WARP per destination node ----------
__global__ void gat1_agg_fused(const int* __restrict__ p, const int* __restrict__ aff,
                               const float* __restrict__ es, const float* __restrict__ ed,
                               const int* __restrict__ srcA,
                               const float* __restrict__ Pp1, const float* __restrict__ Pa1,
                               const float* __restrict__ c1, const float* __restrict__ bias,
                               float* __restrict__ out)
{
    int bn = (blockIdx.x * blockDim.x + threadIdx.x) >> 5;
    int lane = threadIdx.x & 31;
    if (bn >= cBN) return;
    int b = bn / cN, n = bn % cN;
    int o0 = g_off[n];
    int deg = g_off[n + 1] - o0;
    if (deg > 4) deg = 4;

    int ipj = 0, iaj = 0, bsj = 0;
    if (lane < deg) {
        int s = srcA[g_lst[o0 + lane]];
        bsj = b * cN + s;
        ipj = p[bsj];
        iaj = aff[bsj];
    }
    int ip[4], ia[4], bs[4];
#pragma unroll
    for (int j = 0; j < 4; j++) {
        ip[j] = __shfl_sync(0xffffffffu, ipj, j);
        ia[j] = __shfl_sync(0xffffffffu, iaj, j);
        bs[j] = __shfl_sync(0xffffffffu, bsj, j);
    }

    float w0 = 0.f, w1 = 0.f, w2 = 0.f, w3 = 0.f, winv = 1.f;
    if (lane < 8) {
        float edv = ed[bn * 8 + lane];
        float l[4];
        float mx = -1e30f;
        for (int j = 0; j < deg; j++) {
            float lv = es[bs[j] * 8 + lane] + edv;
            lv = lv > 0.f ? lv : 0.2f * lv;
            l[j] = lv;
            mx = fmaxf(mx, lv);
        }
        float sum = 0.f;
        for (int j = 0; j < deg; j++) { l[j] = expf(l[j] - mx); sum += l[j]; }
        w0 = l[0]; if (deg > 1) w1 = l[1]; if (deg > 2) w2 = l[2]; if (deg > 3) w3 = l[3];
        winv = 1.f / sum;
    }

    const size_t base = (size_t)bn * 1024;
#pragma unroll
    for (int c = 0; c < 8; c++) {
        float wj[4];
        wj[0] = __shfl_sync(0xffffffffu, w0, c);
        wj[1] = __shfl_sync(0xffffffffu, w1, c);
        wj[2] = __shfl_sync(0xffffffffu, w2, c);
        wj[3] = __shfl_sync(0xffffffffu, w3, c);
        float inv = __shfl_sync(0xffffffffu, winv, c);
        int fo = c * 128 + lane * 4;
        float4 acc = make_float4(0.f, 0.f, 0.f, 0.f);
        for (int j = 0; j < deg; j++) {
            float4 a = *(const float4*)(Pp1 + (size_t)ip[j] * 1024 + fo);
            float4 cc = *(const float4*)(Pa1 + (size_t)ia[j] * 1024 + fo);
            float ww = wj[j];
            acc.x = fmaf(ww, a.x + cc.x, acc.x);
            acc.y = fmaf(ww, a.y + cc.y, acc.y);
            acc.z = fmaf(ww, a.z + cc.z, acc.z);
            acc.w = fmaf(ww, a.w + cc.w, acc.w);
        }
        float4 cv = *(const float4*)(c1 + fo);
        float4 bi = *(const float4*)(bias + fo);
        float4 v;
        v.x = acc.x * inv + cv.x + bi.x;
        v.y = acc.y * inv + cv.y + bi.y;
        v.z = acc.z * inv + cv.z + bi.z;
        v.w = acc.w * inv + cv.w + bi.w;
        v.x = v.x > 0.f ? v.x : (expf(v.x) - 1.f);
        v.y = v.y > 0.f ? v.y : (expf(v.y) - 1.f);
        v.z = v.z > 0.f ? v.z : (expf(v.z) - 1.f);
        v.w = v.w > 0.f ? v.w : (expf(v.w) - 1.f);
        *(float4*)(out + base + fo) = v;
    }
}

// ------------------------- attention logits (GAT2), float4 -------------------------
__global__ void scores_kernel(const float* __restrict__ h, const float* __restrict__ a_s,
                              const float* __restrict__ a_d, float* __restrict__ es,
                              float* __restrict__ ed, int Hh, int Fo)
{
    int gw = (blockIdx.x * blockDim.x + threadIdx.x) >> 5;
    int lane = threadIdx.x & 31;
    if (gw >= cBN * Hh) return;
    int hh = gw % Hh;
    const float* hp = h + (size_t)gw * Fo;
    float ss = 0.f, sd = 0.f;
    for (int f0 = lane * 4; f0 < Fo; f0 += 128) {
        float4 hv = *(const float4*)(hp + f0);
        float4 as = *(const float4*)(a_s + hh * Fo + f0);
        float4 ad = *(const float4*)(a_d + hh * Fo + f0);
        ss = fmaf(hv.x, as.x, ss); ss = fmaf(hv.y, as.y, ss);
        ss = fmaf(hv.z, as.z, ss); ss = fmaf(hv.w, as.w, ss);
        sd = fmaf(hv.x, ad.x, sd); sd = fmaf(hv.y, ad.y, sd);
        sd = fmaf(hv.z, ad.z, sd); sd = fmaf(hv.w, ad.w, sd);
    }
    for (int o = 16; o; o >>= 1) {
        ss += __shfl_xor_sync(0xffffffffu, ss, o);
        sd += __shfl_xor_sync(0xffffffffu, sd, o);
    }
    if (lane == 0) { es[gw] = ss; ed[gw] = sd; }
}

// ------------------------- GAT2 aggregation, float4 -------------------------
__global__ void gat_agg(const float* __restrict__ h, const float* __restrict__ es,
                        const float* __restrict__ ed, const int* __restrict__ srcA,
                        const float* __restrict__ bias, float* __restrict__ out,
                        int Hh, int Fo, int elu)
{
    int gw = (blockIdx.x * blockDim.x + threadIdx.x) >> 5;
    int lane = threadIdx.x & 31;
    if (gw >= cBN * Hh) return;
    int hh = gw % Hh;
    int bn = gw / Hh;
    int b = bn / cN, n = bn % cN;
    int o0 = g_off[n];
    int deg = g_off[n + 1] - o0;
    if (deg > 4) deg = 4;
    int ssrc[4];
    float w[4];
    float edv = ed[(size_t)bn * Hh + hh];
    float mx = -1e30f;
    for (int j = 0; j < deg; j++) {
        int s = srcA[g_lst[o0 + j]];
        ssrc[j] = s;
        float l = es[((size_t)b * cN + s) * Hh + hh] + edv;
        l = l > 0.f ? l : 0.2f * l;
        w[j] = l;
        mx = fmaxf(mx, l);
    }
    float sum = 0.f;
    for (int j = 0; j < deg; j++) { w[j] = expf(w[j] - mx); sum += w[j]; }
    float inv = 1.f / sum;
    for (int f0 = lane * 4; f0 < Fo; f0 += 128) {
        float4 acc = make_float4(0.f, 0.f, 0.f, 0.f);
        for (int j = 0; j < deg; j++) {
            float4 hv = *(const float4*)(h + (((size_t)b * cN + ssrc[j]) * Hh + hh) * Fo + f0);
            float wj = w[j];
            acc.x = fmaf(wj, hv.x, acc.x); acc.y = fmaf(wj, hv.y, acc.y);
            acc.z = fmaf(wj, hv.z, acc.z); acc.w = fmaf(wj, hv.w, acc.w);
        }
        float4 bi = *(const float4*)(bias + hh * Fo + f0);
        float4 v;
        v.x = acc.x * inv + bi.x; v.y = acc.y * inv + bi.y;
        v.z = acc.z * inv + bi.z; v.w = acc.w * inv + bi.w;
        if (elu) {
            v.x = v.x > 0.f ? v.x : (expf(v.x) - 1.f);
            v.y = v.y > 0.f ? v.y : (expf(v.y) - 1.f);
            v.z = v.z > 0.f ? v.z : (expf(v.z) - 1.f);
            v.w = v.w > 0.f ? v.w : (expf(v.w) - 1.f);
        }
        *(float4*)(out + (size_t)gw * Fo + f0) = v;
    }
}

// ------------------------- cluster LSTM (vectorized cooperative DSMEM push) -----------------
// Per step: compute threads write h LOCALLY; after __syncthreads, 224 threads each push one
// float4 (7 peers x 4 batches x 8 segments) via st.shared::cluster.v4 — 224 remote ops/step
// instead of 1024 scalar ones. One barrier.cluster per step for ordering.
__global__ void __cluster_dims__(8, 1, 1) __launch_bounds__(256, 1)
lstm_cluster(const float* __restrict__ pre, const float* __restrict__ WhhT,
             float* __restrict__ hseq)
{
    __shared__ float hbuf[2][BPC][256];
    const int tid = threadIdx.x;
    const int hi = tid >> 3;
    const int kc = tid & 7;
    unsigned rank;
    asm("mov.u32 %0, %%cluster_ctarank;" : "=r"(rank));
    const int b0 = (blockIdx.x >> 3) * BPC;
    const int hg = (int)rank * 32 + hi;

    float w[4][32];
#pragma unroll
    for (int g = 0; g < 4; g++)
#pragma unroll
        for (int k = 0; k < 32; k++)
            w[g][k] = WhhT[(size_t)(kc * 32 + k) * 1024 + g * 256 + hg];

    for (int i = tid; i < 2 * BPC * 256; i += 256)
        ((float*)hbuf)[i] = 0.f;

    float cst = 0.f;
    const unsigned hb_base = smem_u32(hbuf);

    // cooperative push assignment: tid in [0,224) pushes one float4 to one peer
    const int pi = tid >> 5;                 // 0..7 (peer slot; 7 used)
    const int pl = tid & 31;
    const int pbch = pl >> 3;                // batch 0..3
    const int pseg = pl & 7;                 // segment 0..7 (4 floats each)
    int peer = (pi >= (int)rank) ? pi + 1 : pi;
    const bool doPush = (pi < 7);
    // source/dest offset within hbuf for parity P: ((P*BPC + pbch)*256 + rank*32 + pseg*4)*4 bytes
    const unsigned pushOffBase = (unsigned)(((pbch) * 256 + (int)rank * 32 + pseg * 4) * 4);

    CLUSTER_SYNC();

    for (int t = 0; t < cN; t++) {
        const int pb = t & 1;
        float pg0 = 0.f, pg1 = 0.f, pg2 = 0.f, pg3 = 0.f;
        if (kc < BPC) {
            const float* pr = pre + ((size_t)((b0 + kc) * cN + t)) * 1024 + hg;
            pg0 = pr[0]; pg1 = pr[256]; pg2 = pr[512]; pg3 = pr[768];
        }

        float acc[4][BPC];
#pragma unroll
        for (int g = 0; g < 4; g++)
#pragma unroll
            for (int b = 0; b < BPC; b++) acc[g][b] = 0.f;

#pragma unroll
        for (int b = 0; b < BPC; b++) {
            const float* hp = &hbuf[pb][b][kc * 32];
#pragma unroll
            for (int k = 0; k < 32; k += 4) {
                float4 h4 = *(const float4*)(hp + k);
#pragma unroll
                for (int g = 0; g < 4; g++) {
                    acc[g][b] = fmaf(h4.x, w[g][k + 0], acc[g][b]);
                    acc[g][b] = fmaf(h4.y, w[g][k + 1], acc[g][b]);
                    acc[g][b] = fmaf(h4.z, w[g][k + 2], acc[g][b]);
                    acc[g][b] = fmaf(h4.w, w[g][k + 3], acc[g][b]);
                }
            }
        }

#pragma unroll
        for (int o = 1; o < 8; o <<= 1)
#pragma unroll
            for (int g = 0; g < 4; g++)
#pragma unroll
                for (int b = 0; b < BPC; b++)
                    acc[g][b] += __shfl_xor_sync(0xffffffffu, acc[g][b], o);

        if (kc < BPC) {
            const int b = kc;
            float iv = acc[0][b] + pg0;
            float fv = acc[1][b] + pg1;
            float gv = acc[2][b] + pg2;
            float ov = acc[3][b] + pg3;
            float ig = 1.f / (1.f + __expf(-iv));
            float fg = 1.f / (1.f + __expf(-fv));
            float og = 1.f / (1.f + __expf(-ov));
            cst = fg * cst + ig * tanhf(gv);
            float hval = og * tanhf(cst);
            hseq[((size_t)((b0 + b) * cN + t)) * 256 + hg] = hval;
            hbuf[1 - pb][b][hg] = hval;         // LOCAL write only (self copy)
        }
        __syncthreads();                        // local h slice complete

        if (doPush) {
            const unsigned off = (unsigned)((1 - pb) * BPC * 256 * 4) + pushOffBase;
            float4 v = *(const float4*)((const char*)hbuf + off);
            asm volatile(
                "{ .reg .b32 ra; mapa.shared::cluster.u32 ra, %0, %1; "
                "st.shared::cluster.v4.f32 [ra], {%2, %3, %4, %5}; }"
                :: "r"(hb_base + off), "r"(peer),
                   "f"(v.x), "f"(v.y), "f"(v.z), "f"(v.w)
                : "memory");
        }
        CLUSTER_SYNC();    // remote pushes visible cluster-wide; step t+1 may read
    }
}

// ------------------------- output head, float4 -------------------------
__global__ void out_kernel(const int* __restrict__ qn, const int* __restrict__ pn,
                           const float* __restrict__ Wout, const float* __restrict__ b_out,
                           const float* __restrict__ hseq, const float* __restrict__ outp,
                           const float* __restrict__ outq, float* __restrict__ y)
{
    int gw = (blockIdx.x * blockDim.x + threadIdx.x) >> 5;
    int lane = threadIdx.x & 31;
    if (gw >= cBN) return;
    const float* hp = hseq + (size_t)gw * 256;
    float acc = 0.f;
#pragma unroll
    for (int f0 = lane * 4; f0 < 256; f0 += 128) {
        float4 hv = *(const float4*)(hp + f0);
        float4 wv = *(const float4*)(Wout + f0);
        acc = fmaf(hv.x, wv.x, acc); acc = fmaf(hv.y, wv.y, acc);
        acc = fmaf(hv.z, wv.z, acc); acc = fmaf(hv.w, wv.w, acc);
    }
    for (int o = 16; o; o >>= 1) acc += __shfl_xor_sync(0xffffffffu, acc, o);
    if (lane == 0) {
        float v = acc + outq[qn[gw]] + outp[pn[gw]] + b_out[0];
        y[gw] = 1.f / (1.f + expf(-v));
    }
}

// ------------------------- host orchestration -------------------------
static inline dim3 tg(int M, int N) { return dim3(N / 128, (M + 127) / 128); }

extern "C" void kernel_launch(void* const* d_in, const int* in_sizes, int n_in,
                              void* d_out, int out_size)
{
    const int*   p       = (const int*)d_in[1];
    const int*   q       = (const int*)d_in[2];
    const int*   r       = (const int*)d_in[3];
    const int*   aff     = (const int*)d_in[4];
    const int*   q_next  = (const int*)d_in[5];
    const int*   p_next  = (const int*)d_in[6];
    const int*   src     = (const int*)d_in[7];
    const int*   dst     = (const int*)d_in[8];
    const float* emb_p   = (const float*)d_in[9];
    const float* emb_q   = (const float*)d_in[10];
    const float* emb_r   = (const float*)d_in[11];
    const float* emb_aff = (const float*)d_in[12];
    const float* W_affcat= (const float*)d_in[13];
    const float* b_affcat= (const float*)d_in[14];
    const float* W_g1    = (const float*)d_in[15];
    const float* a_src1  = (const float*)d_in[16];
    const float* a_dst1  = (const float*)d_in[17];
    const float* b_g1    = (const float*)d_in[18];
    const float* W_g2    = (const float*)d_in[19];
    const float* a_src2  = (const float*)d_in[20];
    const float* a_dst2  = (const float*)d_in[21];
    const float* b_g2    = (const float*)d_in[22];
    const float* W_ih    = (const float*)d_in[23];
    const float* W_hh    = (const float*)d_in[24];
    const float* b_ih    = (const float*)d_in[25];
    const float* b_hh    = (const float*)d_in[26];
    const float* W_out   = (const float*)d_in[27];
    const float* b_out   = (const float*)d_in[28];
    int E = in_sizes[7];

    float *WhhT, *Wg1T, *WaT, *Wg2T, *WcT, *c1, *Pp1, *Pa1, *Pih_p, *Pih_q, *Pih_r;
    float *Ssp, *Sdp, *Ssa, *Sda, *cs1, *bsum;
    float *big1, *x1, *h2, *x2, *es1, *ed1, *es2, *ed2, *hseq, *outp, *outq;
    cudaGetSymbolAddress((void**)&WhhT,  g_WhhT);
    cudaGetSymbolAddress((void**)&Wg1T,  g_Wg1T);
    cudaGetSymbolAddress((void**)&WaT,   g_WaT);
    cudaGetSymbolAddress((void**)&Wg2T,  g_Wg2T);
    cudaGetSymbolAddress((void**)&WcT,   g_WcT);
    cudaGetSymbolAddress((void**)&c1,    g_c1);
    cudaGetSymbolAddress((void**)&Pp1,   g_Pp1);
    cudaGetSymbolAddress((void**)&Pa1,   g_Pa1);
    cudaGetSymbolAddress((void**)&Pih_p, g_Pih_p);
    cudaGetSymbolAddress((void**)&Pih_q, g_Pih_q);
    cudaGetSymbolAddress((void**)&Pih_r, g_Pih_r);
    cudaGetSymbolAddress((void**)&Ssp,   g_Ssp);
    cudaGetSymbolAddress((void**)&Sdp,   g_Sdp);
    cudaGetSymbolAddress((void**)&Ssa,   g_Ssa);
    cudaGetSymbolAddress((void**)&Sda,   g_Sda);
    cudaGetSymbolAddress((void**)&cs1,   g_cs1);
    cudaGetSymbolAddress((void**)&bsum,  g_bsum);
    cudaGetSymbolAddress((void**)&big1,  g_big1);
    cudaGetSymbolAddress((void**)&x1,    g_x1);
    cudaGetSymbolAddress((void**)&h2,    g_h2);
    cudaGetSymbolAddress((void**)&x2,    g_x2);
    cudaGetSymbolAddress((void**)&es1,   g_es1);
    cudaGetSymbolAddress((void**)&ed1,   g_ed1);
    cudaGetSymbolAddress((void**)&es2,   g_es2);
    cudaGetSymbolAddress((void**)&ed2,   g_ed2);
    cudaGetSymbolAddress((void**)&hseq,  g_hseq);
    cudaGetSymbolAddress((void**)&outp,  g_outp);
    cudaGetSymbolAddress((void**)&outq,  g_outq);

    cudaFuncSetAttribute(tgemm, cudaFuncAttributeMaxDynamicSharedMemorySize, TG_SMEM);
    cudaFuncSetAttribute(tgemm_pre, cudaFuncAttributeMaxDynamicSharedMemorySize, TG_SMEM);

    // --- dependency-free launches first ---
    rowdot_kernel<<<(NP*32 + 255)/256, 256>>>(emb_p, W_out + 512, outp, NP);   // 1
    rowdot_kernel<<<(NQ*32 + 255)/256, 256>>>(emb_q, W_out + 256, outq, NQ);   // 2
    tgemm<<<tg(NP, 1024), 256, TG_SMEM>>>(emb_p, 256, W_ih,       1024, Pih_p, 1024, NP, 1024, 256, 0); // 3
    tgemm<<<tg(NQ, 1024), 256, TG_SMEM>>>(emb_q, 256, W_ih + 256, 1024, Pih_q, 1024, NQ, 1024, 256, 0); // 4
    tgemm<<<tg(2,  1024), 256, TG_SMEM>>>(emb_r, 256, W_ih + 512, 1024, Pih_r, 1024, 2,  1024, 256, 0); // 5
    csr_build<<<1, 512>>>(dst, E);                                             // 6

    // --- weight preprocessing (small) ---
    transpose_k<<<(1024*256)/256, 256>>>(W_hh, WhhT, 1024, 256);
    transpose_k<<<(256*1024)/256, 256>>>(W_g1, Wg1T, 256, 1024);
    transpose_k<<<(512*256)/256,  256>>>(W_affcat, WaT, 512, 256);
    transpose_k<<<(1024*256)/256, 256>>>(W_g2, Wg2T, 1024, 256);

    sgemm_t<<<dim3(8, 4), 256>>>(Wg1T, WaT, WcT, 1024, 256, 512, 0);
    vecmat_k<<<4, 256>>>(b_affcat, W_g1, c1, 256, 1024);
    bsum_k<<<1, 1024>>>(b_ih, b_hh, bsum);

    // --- remaining per-table pre-projections (tf32 tensor cores) ---
    tgemm<<<tg(NP, 1024), 256, TG_SMEM>>>(emb_p,   256, WcT,       512, Pp1, 1024, NP, 1024, 256, 0);
    tgemm<<<tg(NA, 1024), 256, TG_SMEM>>>(emb_aff, 256, WcT + 256, 512, Pa1, 1024, NA, 1024, 256, 0);

    // per-table attention score tables
    score_tab<<<NP, 256>>>(Pp1, a_src1, a_dst1, Ssp, Sdp);
    score_tab<<<NA, 256>>>(Pa1, a_src1, a_dst1, Ssa, Sda);
    cvec_k<<<1, 512>>>(c1, a_src1, a_dst1, cs1);

    // --- GAT layer 1: logits + fused aggregation straight from tables ---
    scores_gather<<<(cBN*8 + 255)/256, 256>>>(p, aff, Ssp, Ssa, Sdp, Sda, cs1, es1, ed1);
    gat1_agg_fused<<<(cBN*32 + 255)/256, 256>>>(p, aff, es1, ed1, src, Pp1, Pa1, c1, b_g1, x1);

    // --- GAT layer 2 ---
    tgemm<<<tg(cBN, 256), 256, TG_SMEM>>>(x1, 1024, Wg2T, 1024, h2, 256, cBN, 256, 1024, 0);
    scores_kernel<<<(cBN*32)/256, 256>>>(h2, a_src2, a_dst2, es2, ed2, 1, 256);
    gat_agg<<<(cBN*32)/256, 256>>>(h2, es2, ed2, src, b_g2, x2, 1, 256, 0);

    // --- LSTM input: GEMM with fused gather-epilogue ---
    tgemm_pre<<<tg(cBN, 1024), 256, TG_SMEM>>>(x2, 256, W_ih + 768, 1024, big1, 1024,
                                               cBN, 1024, 256,
                                               p, q, r, Pih_p, Pih_q, Pih_r, bsum);

    // --- LSTM recurrence (vectorized DSMEM exchange) ---
    lstm_cluster<<<128, 256>>>(big1, WhhT, hseq);

    // --- output head ---
    out_kernel<<<(cBN*32)/256, 256>>>(q_next, p_next, W_out, b_out, hseq, outp, outq,
                                      (float*)d_out);
}

// round 16
// speedup vs baseline: 2.5513x; 1.3016x over previous
#include <cuda_runtime.h>
#include <math.h>

// Problem constants (fixed by the dataset)
#define cB 64
#define cN 499
#define cBN (cB*cN)          // 31936 tokens
#define NP 10001
#define NQ 2001
#define NA 11

#define BPC 4                // batches per cluster (16 clusters x 8 CTAs x BPC = 64)
#define BKK 16               // FFMA GEMM k-tile
#define TG_STAGE 18432       // tf32 GEMM: bytes per smem stage (128 rows x 36 floats)
#define TG_SMEM  73728       // 2 ops x 2 stages x 18432

// ------------------------- device scratch (no cudaMalloc allowed) -------------------------
__device__ __align__(16) float g_WhhT[256*1024];      // W_hh transposed: [k][gate]
__device__ __align__(16) float g_Wg1T[1024*256];      // W_g1^T  [n][o]
__device__ __align__(16) float g_WaT [256*512];       // W_affcat^T [o][i]
__device__ __align__(16) float g_Wg2T[256*1024];      // W_g2^T  [n][k]
__device__ __align__(16) float g_WcT [1024*512];      // (W_affcat @ W_g1)^T : [n][i]
__device__ __align__(16) float g_c1[1024];            // b_affcat @ W_g1
__device__ __align__(16) float g_Pp1[(size_t)NP*1024];   // emb_p @ Wc_p
__device__ __align__(16) float g_Pa1[NA*1024];           // emb_aff @ Wc_aff
__device__ __align__(16) float g_Pih_p[(size_t)NP*1024]; // emb_p @ W_ihT[0:256]
__device__ __align__(16) float g_Pih_q[(size_t)NQ*1024]; // emb_q @ W_ihT[256:512]
__device__ __align__(16) float g_Pih_r[2*1024];          // emb_r @ W_ihT[512:768]
__device__ __align__(16) float g_Ssp[NP*8];           // Pp1 . a_src1 (per head)
__device__ __align__(16) float g_Sdp[NP*8];           // Pp1 . a_dst1
__device__ __align__(16) float g_Ssa[NA*8];           // Pa1 . a_src1
__device__ __align__(16) float g_Sda[NA*8];           // Pa1 . a_dst1
__device__ __align__(16) float g_cs1[16];             // c1.a_src1 per head, then c1.a_dst1
__device__ __align__(16) float g_bsum[1024];          // b_ih + b_hh
__device__ __align__(16) float g_outp[NP];            // emb_p . W_out[512:768]
__device__ __align__(16) float g_outq[NQ];            // emb_q . W_out[256:512]
__device__ __align__(16) float g_big1[(size_t)cBN*1024];  // lstm_pre
__device__ __align__(16) float g_x1[(size_t)cBN*1024];
__device__ __align__(16) float g_h2[cBN*256];
__device__ __align__(16) float g_x2[cBN*256];
__device__ __align__(16) float g_es1[cBN*8];
__device__ __align__(16) float g_ed1[cBN*8];
__device__ __align__(16) float g_es2[cBN];
__device__ __align__(16) float g_ed2[cBN];
__device__ __align__(16) float g_hseq[cBN*256];
__device__ int g_off[cN+1];
__device__ int g_lst[4096];

// ------------------------- small helpers -------------------------
__device__ __forceinline__ unsigned smem_u32(const void* p) {
    unsigned a;
    asm("{ .reg .u64 t; cvta.to.shared.u64 t, %1; cvt.u32.u64 %0, t; }" : "=r"(a) : "l"(p));
    return a;
}
__device__ __forceinline__ void cpa16(unsigned dst, const void* src) {
    asm volatile("cp.async.ca.shared.global [%0], [%1], 16;" :: "r"(dst), "l"(src));
}
__device__ __forceinline__ void cpa16z(unsigned dst, const void* src, int n) {
    asm volatile("cp.async.ca.shared.global [%0], [%1], 16, %2;" :: "r"(dst), "l"(src), "r"(n));
}
#define CPA_COMMIT() asm volatile("cp.async.commit_group;" ::: "memory")
#define CLUSTER_SYNC() do { \
    asm volatile("barrier.cluster.arrive.aligned;" ::: "memory"); \
    asm volatile("barrier.cluster.wait.aligned;"   ::: "memory"); } while (0)

__device__ __forceinline__ void ldsm4(unsigned addr, unsigned* r) {
    asm volatile("ldmatrix.sync.aligned.m8n8.x4.shared.b16 {%0,%1,%2,%3}, [%4];"
                 : "=r"(r[0]), "=r"(r[1]), "=r"(r[2]), "=r"(r[3]) : "r"(addr));
}
__device__ __forceinline__ void ldsm2(unsigned addr, unsigned* r) {
    asm volatile("ldmatrix.sync.aligned.m8n8.x2.shared.b16 {%0,%1}, [%2];"
                 : "=r"(r[0]), "=r"(r[1]) : "r"(addr));
}
__device__ __forceinline__ unsigned f2tf(unsigned x) {
    unsigned y;
    asm("cvt.rna.tf32.f32 %0, %1;" : "=r"(y) : "r"(x));
    return y;
}
__device__ __forceinline__ void mma8(float* d, const unsigned* a, const unsigned* b) {
    asm volatile("mma.sync.aligned.m16n8k8.row.col.f32.tf32.tf32.f32 "
                 "{%0,%1,%2,%3}, {%4,%5,%6,%7}, {%8,%9}, {%0,%1,%2,%3};"
                 : "+f"(d[0]), "+f"(d[1]), "+f"(d[2]), "+f"(d[3])
                 : "r"(a[0]), "r"(a[1]), "r"(a[2]), "r"(a[3]), "r"(b[0]), "r"(b[1]));
}

// ------------------------- generic transpose -------------------------
__global__ void transpose_k(const float* __restrict__ in, float* __restrict__ out, int R, int C)
{
    int idx = blockIdx.x * blockDim.x + threadIdx.x;
    if (idx >= R * C) return;
    int c = idx / R;
    int r = idx - c * R;
    out[idx] = in[r * C + c];
}

// ------------------------- tf32 tensor-core GEMM core -------------------------
struct TGAcc { float a[4][4][4]; };

__device__ __forceinline__ void tgemm_main(const float* __restrict__ A, int lda,
                                           const float* __restrict__ Bn, int ldbn,
                                           int M, int K, int m0, int n0, TGAcc& AC)
{
    extern __shared__ float dynsm[];
    const unsigned smb = smem_u32(dynsm);
    const int tid = threadIdx.x, lane = tid & 31, wid = tid >> 5;
    const int wm = wid & 1, wn = wid >> 1;

    unsigned dOff[4];
    const float* sA[4];
    const float* sB[4];
    int vA[4];
#pragma unroll
    for (int i = 0; i < 4; i++) {
        int qd = tid + 256 * i;
        int row = qd >> 3, kq = qd & 7;
        dOff[i] = row * 144 + kq * 16;
        int ra = m0 + row;
        vA[i] = (ra < M) ? 16 : 0;
        sA[i] = A + (size_t)(vA[i] ? ra : 0) * lda + kq * 4;
        sB[i] = Bn + (size_t)(n0 + row) * ldbn + kq * 4;
    }

#pragma unroll
    for (int mt = 0; mt < 4; mt++)
#pragma unroll
        for (int nt = 0; nt < 4; nt++)
#pragma unroll
            for (int j = 0; j < 4; j++) AC.a[mt][nt][j] = 0.f;

#pragma unroll
    for (int i = 0; i < 4; i++) {
        cpa16z(smb + dOff[i], sA[i], vA[i]);
        cpa16z(smb + 2 * TG_STAGE + dOff[i], sB[i], 16);
    }
    CPA_COMMIT();

    const int aRowOff = wm * 64 + (lane & 7) + ((lane >> 3) & 1) * 8;
    const int aColB = (lane >> 4) * 16;
    const int bRowOff = wn * 32 + (lane & 7);
    const int bColB = ((lane >> 3) & 1) * 16;

    const int nst = K / 32;
    for (int st = 0; st < nst; st++) {
        const int buf = st & 1;
        if (st + 1 < nst) {
            const int k0 = (st + 1) * 32;
            const unsigned nb = (buf ^ 1) * TG_STAGE;
#pragma unroll
            for (int i = 0; i < 4; i++) {
                cpa16z(smb + nb + dOff[i], sA[i] + k0, vA[i]);
                cpa16z(smb + 2 * TG_STAGE + nb + dOff[i], sB[i] + k0, 16);
            }
            CPA_COMMIT();
            asm volatile("cp.async.wait_group 1;" ::: "memory");
        } else {
            asm volatile("cp.async.wait_group 0;" ::: "memory");
        }
        __syncthreads();
        const unsigned ab = smb + buf * TG_STAGE;
        const unsigned bb = smb + 2 * TG_STAGE + buf * TG_STAGE;
#pragma unroll
        for (int ks = 0; ks < 4; ks++) {
            unsigned af[4][4], bf[4][2];
#pragma unroll
            for (int mt = 0; mt < 4; mt++) {
                ldsm4(ab + (unsigned)((aRowOff + mt * 16) * 144 + aColB + ks * 32), af[mt]);
                af[mt][0] = f2tf(af[mt][0]); af[mt][1] = f2tf(af[mt][1]);
                af[mt][2] = f2tf(af[mt][2]); af[mt][3] = f2tf(af[mt][3]);
            }
#pragma unroll
            for (int nt = 0; nt < 4; nt++) {
                ldsm2(bb + (unsigned)((bRowOff + nt * 8) * 144 + bColB + ks * 32), bf[nt]);
                bf[nt][0] = f2tf(bf[nt][0]); bf[nt][1] = f2tf(bf[nt][1]);
            }
#pragma unroll
            for (int mt = 0; mt < 4; mt++)
#pragma unroll
                for (int nt = 0; nt < 4; nt++)
                    mma8(AC.a[mt][nt], af[mt], bf[nt]);
        }
        __syncthreads();
    }
}

// plain variant — 2 CTAs/SM
__global__ __launch_bounds__(256, 2) void tgemm(const float* __restrict__ A, int lda,
                                                const float* __restrict__ Bn, int ldbn,
                                                float* __restrict__ C, int ldc,
                                                int M, int N, int K, int accum)
{
    const int lane = threadIdx.x & 31, wid = threadIdx.x >> 5;
    const int wm = wid & 1, wn = wid >> 1;
    const int m0 = blockIdx.y * 128, n0 = blockIdx.x * 128;
    TGAcc AC;
    tgemm_main(A, lda, Bn, ldbn, M, K, m0, n0, AC);

    const int g = lane >> 2, c2 = (lane & 3) * 2;
#pragma unroll
    for (int mt = 0; mt < 4; mt++) {
        int r0 = m0 + wm * 64 + mt * 16 + g;
#pragma unroll
        for (int nt = 0; nt < 4; nt++) {
            int col = n0 + wn * 32 + nt * 8 + c2;
            if (r0 < M) {
                float2* pp = (float2*)(C + (size_t)r0 * ldc + col);
                float2 v = make_float2(AC.a[mt][nt][0], AC.a[mt][nt][1]);
                if (accum) { float2 o = *pp; v.x += o.x; v.y += o.y; }
                *pp = v;
            }
            if (r0 + 8 < M) {
                float2* pp = (float2*)(C + (size_t)(r0 + 8) * ldc + col);
                float2 v = make_float2(AC.a[mt][nt][2], AC.a[mt][nt][3]);
                if (accum) { float2 o = *pp; v.x += o.x; v.y += o.y; }
                *pp = v;
            }
        }
    }
}

// fused-epilogue variant: C = A@B + Tp[fp[m]] + Tq[fq[m]] + Tr[fr[m]] + bsum  (lstm pre)
__global__ __launch_bounds__(256, 2) void tgemm_pre(const float* __restrict__ A, int lda,
                                                    const float* __restrict__ Bn, int ldbn,
                                                    float* __restrict__ C, int ldc,
                                                    int M, int N, int K,
                                                    const int* __restrict__ fp,
                                                    const int* __restrict__ fq,
                                                    const int* __restrict__ fr,
                                                    const float* __restrict__ Tp,
                                                    const float* __restrict__ Tq,
                                                    const float* __restrict__ Tr,
                                                    const float* __restrict__ bsum)
{
    const int lane = threadIdx.x & 31, wid = threadIdx.x >> 5;
    const int wm = wid & 1, wn = wid >> 1;
    const int m0 = blockIdx.y * 128, n0 = blockIdx.x * 128;
    TGAcc AC;
    tgemm_main(A, lda, Bn, ldbn, M, K, m0, n0, AC);

    const int g = lane >> 2, c2 = (lane & 3) * 2;
#pragma unroll
    for (int mt = 0; mt < 4; mt++) {
        int r0 = m0 + wm * 64 + mt * 16 + g;
        bool ok0 = r0 < M, ok1 = (r0 + 8) < M;
        size_t p0 = 0, q0 = 0, rr0 = 0, p1 = 0, q1 = 0, rr1 = 0;
        if (ok0) { p0 = (size_t)fp[r0] * 1024; q0 = (size_t)fq[r0] * 1024; rr0 = (size_t)fr[r0] * 1024; }
        if (ok1) { p1 = (size_t)fp[r0+8] * 1024; q1 = (size_t)fq[r0+8] * 1024; rr1 = (size_t)fr[r0+8] * 1024; }
#pragma unroll
        for (int nt = 0; nt < 4; nt++) {
            int col = n0 + wn * 32 + nt * 8 + c2;
            float2 bs = *(const float2*)(bsum + col);
            if (ok0) {
                float2 tp = *(const float2*)(Tp + p0 + col);
                float2 tq = *(const float2*)(Tq + q0 + col);
                float2 tr = *(const float2*)(Tr + rr0 + col);
                float2 v = make_float2(AC.a[mt][nt][0] + tp.x + tq.x + tr.x + bs.x,
                                       AC.a[mt][nt][1] + tp.y + tq.y + tr.y + bs.y);
                *(float2*)(C + (size_t)r0 * ldc + col) = v;
            }
            if (ok1) {
                float2 tp = *(const float2*)(Tp + p1 + col);
                float2 tq = *(const float2*)(Tq + q1 + col);
                float2 tr = *(const float2*)(Tr + rr1 + col);
                float2 v = make_float2(AC.a[mt][nt][2] + tp.x + tq.x + tr.x + bs.x,
                                       AC.a[mt][nt][3] + tp.y + tq.y + tr.y + bs.y);
                *(float2*)(C + (size_t)(r0 + 8) * ldc + col) = v;
            }
        }
    }
}

// ------------------------- FFMA SGEMM (exact; Wc composition only) -------------------------
__global__ __launch_bounds__(256, 2) void sgemm_t(const float* __restrict__ A,
                                                  const float* __restrict__ Bm,
                                                  float* __restrict__ C,
                                                  int M, int K, int Nc, int accum)
{
    __shared__ float As[2][BKK][128];
    __shared__ float Bs[2][BKK][128];
    const int tid = threadIdx.x;
    const int m0 = blockIdx.x * 128, n0 = blockIdx.y * 128;
    const int tRow = (tid >> 4) * 8, tCol = (tid & 15) * 8;

    const int am0 = tid >> 2, ak = (tid & 3) * 4;
    const int am1 = am0 + 64;
    const int br0 = tid >> 5, bc = (tid & 31) * 4;
    const int br1 = br0 + 8;

    const bool v0 = (m0 + am0) < M, v1 = (m0 + am1) < M;
    const float* A0 = A + (size_t)(v0 ? m0 + am0 : 0) * K + ak;
    const float* A1 = A + (size_t)(v1 ? m0 + am1 : 0) * K + ak;
    const float* B0 = Bm + (size_t)br0 * Nc + n0 + bc;
    const float* B1 = Bm + (size_t)br1 * Nc + n0 + bc;

    unsigned sB00 = smem_u32(&Bs[0][br0][bc]), sB01 = smem_u32(&Bs[0][br1][bc]);
    unsigned sB10 = smem_u32(&Bs[1][br0][bc]), sB11 = smem_u32(&Bs[1][br1][bc]);

    float acc[8][8];
#pragma unroll
    for (int i = 0; i < 8; i++)
#pragma unroll
        for (int j = 0; j < 8; j++) acc[i][j] = 0.f;

    const float4 z4 = make_float4(0.f, 0.f, 0.f, 0.f);
    float4 a0 = v0 ? *(const float4*)A0 : z4;
    float4 a1 = v1 ? *(const float4*)A1 : z4;
    cpa16(sB00, B0);
    cpa16(sB01, B1);
    CPA_COMMIT();

    const int nt = K / BKK;
    for (int it = 0; it < nt; it++) {
        const int buf = it & 1;
        As[buf][ak + 0][am0] = a0.x; As[buf][ak + 1][am0] = a0.y;
        As[buf][ak + 2][am0] = a0.z; As[buf][ak + 3][am0] = a0.w;
        As[buf][ak + 0][am1] = a1.x; As[buf][ak + 1][am1] = a1.y;
        As[buf][ak + 2][am1] = a1.z; As[buf][ak + 3][am1] = a1.w;
        if (it + 1 < nt) {
            const int k0 = (it + 1) * BKK;
            a0 = v0 ? *(const float4*)(A0 + k0) : z4;
            a1 = v1 ? *(const float4*)(A1 + k0) : z4;
            cpa16(buf ? sB00 : sB10, B0 + (size_t)k0 * Nc);
            cpa16(buf ? sB01 : sB11, B1 + (size_t)k0 * Nc);
            CPA_COMMIT();
            asm volatile("cp.async.wait_group 1;" ::: "memory");
        } else {
            asm volatile("cp.async.wait_group 0;" ::: "memory");
        }
        __syncthreads();
#pragma unroll
        for (int kk = 0; kk < BKK; kk++) {
            float4 ra0 = *(const float4*)&As[buf][kk][tRow];
            float4 ra1 = *(const float4*)&As[buf][kk][tRow + 4];
            float4 rb0 = *(const float4*)&Bs[buf][kk][tCol];
            float4 rb1 = *(const float4*)&Bs[buf][kk][tCol + 4];
            float ra[8] = {ra0.x, ra0.y, ra0.z, ra0.w, ra1.x, ra1.y, ra1.z, ra1.w};
            float rb[8] = {rb0.x, rb0.y, rb0.z, rb0.w, rb1.x, rb1.y, rb1.z, rb1.w};
#pragma unroll
            for (int i = 0; i < 8; i++)
#pragma unroll
                for (int j = 0; j < 8; j++) acc[i][j] = fmaf(ra[i], rb[j], acc[i][j]);
        }
        __syncthreads();
    }

    for (int i = 0; i < 8; i++) {
        int m = m0 + tRow + i;
        if (m >= M) break;
        float* Crow = C + (size_t)m * Nc + n0 + tCol;
#pragma unroll
        for (int j = 0; j < 8; j += 4) {
            float4 v = make_float4(acc[i][j], acc[i][j+1], acc[i][j+2], acc[i][j+3]);
            if (accum) {
                float4 o = *(float4*)(Crow + j);
                v.x += o.x; v.y += o.y; v.z += o.z; v.w += o.w;
            }
            *(float4*)(Crow + j) = v;
        }
    }
}

// ------------------------- vec @ mat -------------------------
__global__ void vecmat_k(const float* __restrict__ v, const float* __restrict__ Wm,
                         float* __restrict__ out, int K, int Nc)
{
    int n = blockIdx.x * blockDim.x + threadIdx.x;
    if (n >= Nc) return;
    float acc = 0.f;
    for (int k = 0; k < K; k++) acc = fmaf(v[k], Wm[(size_t)k * Nc + n], acc);
    out[n] = acc;
}

// ------------------------- row dot (cols=256), float4 loads -------------------------
__global__ void rowdot_kernel(const float* __restrict__ emb, const float* __restrict__ w,
                              float* __restrict__ out, int rows)
{
    int gw = (blockIdx.x * blockDim.x + threadIdx.x) >> 5;
    int lane = threadIdx.x & 31;
    if (gw >= rows) return;
    const float* e = emb + (size_t)gw * 256;
    float acc = 0.f;
#pragma unroll
    for (int f0 = lane * 4; f0 < 256; f0 += 128) {
        float4 ev = *(const float4*)(e + f0);
        float4 wv = *(const float4*)(w + f0);
        acc = fmaf(ev.x, wv.x, acc); acc = fmaf(ev.y, wv.y, acc);
        acc = fmaf(ev.z, wv.z, acc); acc = fmaf(ev.w, wv.w, acc);
    }
    for (int o = 16; o; o >>= 1) acc += __shfl_xor_sync(0xffffffffu, acc, o);
    if (lane == 0) out[gw] = acc;
}

// ------------------------- per-table score tables (float4) -------------------------
__global__ void score_tab(const float* __restrict__ P, const float* __restrict__ a_s,
                          const float* __restrict__ a_d, float* __restrict__ Ss,
                          float* __restrict__ Sd)
{
    int row = blockIdx.x;
    int h = threadIdx.x >> 5;         // 8 warps = 8 heads
    int lane = threadIdx.x & 31;
    int f0 = h * 128 + lane * 4;
    float4 pv = *(const float4*)(P + (size_t)row * 1024 + f0);
    float4 as = *(const float4*)(a_s + f0);
    float4 ad = *(const float4*)(a_d + f0);
    float ss = pv.x * as.x + pv.y * as.y + pv.z * as.z + pv.w * as.w;
    float sd = pv.x * ad.x + pv.y * ad.y + pv.z * ad.z + pv.w * ad.w;
    for (int o = 16; o; o >>= 1) {
        ss += __shfl_xor_sync(0xffffffffu, ss, o);
        sd += __shfl_xor_sync(0xffffffffu, sd, o);
    }
    if (lane == 0) { Ss[row * 8 + h] = ss; Sd[row * 8 + h] = sd; }
}

// cs1[0..7] = c1.a_src per head, cs1[8..15] = c1.a_dst per head
__global__ void cvec_k(const float* __restrict__ c1, const float* __restrict__ a_s,
                       const float* __restrict__ a_d, float* __restrict__ cs)
{
    int w = threadIdx.x >> 5;         // 16 warps
    int lane = threadIdx.x & 31;
    int h = w & 7;
    const float* a = (w < 8) ? a_s : a_d;
    float acc = 0.f;
#pragma unroll
    for (int f = lane; f < 128; f += 32)
        acc = fmaf(c1[h * 128 + f], a[h * 128 + f], acc);
    for (int o = 16; o; o >>= 1) acc += __shfl_xor_sync(0xffffffffu, acc, o);
    if (lane == 0) cs[w] = acc;
}

__global__ void bsum_k(const float* __restrict__ a, const float* __restrict__ b,
                       float* __restrict__ o)
{
    int i = threadIdx.x;
    o[i] = a[i] + b[i];
}

// es1/ed1 gather
__global__ void scores_gather(const int* __restrict__ p, const int* __restrict__ aff,
                              const float* __restrict__ Ssp, const float* __restrict__ Ssa,
                              const float* __restrict__ Sdp, const float* __restrict__ Sda,
                              const float* __restrict__ cs, float* __restrict__ es,
                              float* __restrict__ ed)
{
    int idx = blockIdx.x * blockDim.x + threadIdx.x;
    if (idx >= cBN * 8) return;
    int bn = idx >> 3, h = idx & 7;
    int pv = p[bn], av = aff[bn];
    es[idx] = Ssp[pv * 8 + h] + Ssa[av * 8 + h] + cs[h];
    ed[idx] = Sdp[pv * 8 + h] + Sda[av * 8 + h] + cs[8 + h];
}

// ------------------------- deterministic CSR of incoming edges -------------------------
__global__ void csr_build(const int* __restrict__ dst, int E)
{
    __shared__ int cnt[cN];
    int tid = threadIdx.x;
    for (int n = tid; n < cN; n += blockDim.x) cnt[n] = 0;
    __syncthreads();
    for (int e = tid; e < E; e += blockDim.x) atomicAdd(&cnt[dst[e]], 1);
    __syncthreads();
    if (tid == 0) {
        int s = 0;
        for (int n = 0; n < cN; n++) { g_off[n] = s; s += cnt[n]; }
        g_off[cN] = s;
    }
    __syncthreads();
    for (int n = tid; n < cN; n += blockDim.x) cnt[n] = 0;
    __syncthreads();
    for (int e = tid; e < E; e += blockDim.x) {
        int d = dst[e];
        int pos = atomicAdd(&cnt[d], 1);
        g_lst[g_off[d] + pos] = e;
    }
    __syncthreads();
    for (int n = tid; n < cN; n += blockDim.x) {
        int o0 = g_off[n], o1 = g_off[n + 1];
        for (int i = o0 + 1; i < o1; i++) {
            int v = g_lst[i], j = i - 1;
            while (j >= o0 && g_lst[j] > v) { g_lst[j + 1] = g_lst[j]; j--; }
            g_lst[j + 1] = v;
        }
    }
}

// ------------------------- GAT1 fused aggregation: one WARP per destination node ----------
__global__ void gat1_agg_fused(const int* __restrict__ p, const int* __restrict__ aff,
                               const float* __restrict__ es, const float* __restrict__ ed,
                               const int* __restrict__ srcA,
                               const float* __restrict__ Pp1, const float* __restrict__ Pa1,
                               const float* __restrict__ c1, const float* __restrict__ bias,
                               float* __restrict__ out)
{
    int bn = (blockIdx.x * blockDim.x + threadIdx.x) >> 5;
    int lane = threadIdx.x & 31;
    if (bn >= cBN) return;
    int b = bn / cN, n = bn % cN;
    int o0 = g_off[n];
    int deg = g_off[n + 1] - o0;
    if (deg > 4) deg = 4;

    int ipj = 0, iaj = 0, bsj = 0;
    if (lane < deg) {
        int s = srcA[g_lst[o0 + lane]];
        bsj = b * cN + s;
        ipj = p[bsj];
        iaj = aff[bsj];
    }
    int ip[4], ia[4], bs[4];
#pragma unroll
    for (int j = 0; j < 4; j++) {
        ip[j] = __shfl_sync(0xffffffffu, ipj, j);
        ia[j] = __shfl_sync(0xffffffffu, iaj, j);
        bs[j] = __shfl_sync(0xffffffffu, bsj, j);
    }

    float w0 = 0.f, w1 = 0.f, w2 = 0.f, w3 = 0.f, winv = 1.f;
    if (lane < 8) {
        float edv = ed[bn * 8 + lane];
        float l[4];
        float mx = -1e30f;
        for (int j = 0; j < deg; j++) {
            float lv = es[bs[j] * 8 + lane] + edv;
            lv = lv > 0.f ? lv : 0.2f * lv;
            l[j] = lv;
            mx = fmaxf(mx, lv);
        }
        float sum = 0.f;
        for (int j = 0; j < deg; j++) { l[j] = expf(l[j] - mx); sum += l[j]; }
        w0 = l[0]; if (deg > 1) w1 = l[1]; if (deg > 2) w2 = l[2]; if (deg > 3) w3 = l[3];
        winv = 1.f / sum;
    }

    const size_t base = (size_t)bn * 1024;
#pragma unroll
    for (int c = 0; c < 8; c++) {
        float wj[4];
        wj[0] = __shfl_sync(0xffffffffu, w0, c);
        wj[1] = __shfl_sync(0xffffffffu, w1, c);
        wj[2] = __shfl_sync(0xffffffffu, w2, c);
        wj[3] = __shfl_sync(0xffffffffu, w3, c);
        float inv = __shfl_sync(0xffffffffu, winv, c);
        int fo = c * 128 + lane * 4;
        float4 acc = make_float4(0.f, 0.f, 0.f, 0.f);
        for (int j = 0; j < deg; j++) {
            float4 a = *(const float4*)(Pp1 + (size_t)ip[j] * 1024 + fo);
            float4 cc = *(const float4*)(Pa1 + (size_t)ia[j] * 1024 + fo);
            float ww = wj[j];
            acc.x = fmaf(ww, a.x + cc.x, acc.x);
            acc.y = fmaf(ww, a.y + cc.y, acc.y);
            acc.z = fmaf(ww, a.z + cc.z, acc.z);
            acc.w = fmaf(ww, a.w + cc.w, acc.w);
        }
        float4 cv = *(const float4*)(c1 + fo);
        float4 bi = *(const float4*)(bias + fo);
        float4 v;
        v.x = acc.x * inv + cv.x + bi.x;
        v.y = acc.y * inv + cv.y + bi.y;
        v.z = acc.z * inv + cv.z + bi.z;
        v.w = acc.w * inv + cv.w + bi.w;
        v.x = v.x > 0.f ? v.x : (expf(v.x) - 1.f);
        v.y = v.y > 0.f ? v.y : (expf(v.y) - 1.f);
        v.z = v.z > 0.f ? v.z : (expf(v.z) - 1.f);
        v.w = v.w > 0.f ? v.w : (expf(v.w) - 1.f);
        *(float4*)(out + base + fo) = v;
    }
}

// ------------------------- attention logits (GAT2), float4 -------------------------
__global__ void scores_kernel(const float* __restrict__ h, const float* __restrict__ a_s,
                              const float* __restrict__ a_d, float* __restrict__ es,
                              float* __restrict__ ed, int Hh, int Fo)
{
    int gw = (blockIdx.x * blockDim.x + threadIdx.x) >> 5;
    int lane = threadIdx.x & 31;
    if (gw >= cBN * Hh) return;
    int hh = gw % Hh;
    const float* hp = h + (size_t)gw * Fo;
    float ss = 0.f, sd = 0.f;
    for (int f0 = lane * 4; f0 < Fo; f0 += 128) {
        float4 hv = *(const float4*)(hp + f0);
        float4 as = *(const float4*)(a_s + hh * Fo + f0);
        float4 ad = *(const float4*)(a_d + hh * Fo + f0);
        ss = fmaf(hv.x, as.x, ss); ss = fmaf(hv.y, as.y, ss);
        ss = fmaf(hv.z, as.z, ss); ss = fmaf(hv.w, as.w, ss);
        sd = fmaf(hv.x, ad.x, sd); sd = fmaf(hv.y, ad.y, sd);
        sd = fmaf(hv.z, ad.z, sd); sd = fmaf(hv.w, ad.w, sd);
    }
    for (int o = 16; o; o >>= 1) {
        ss += __shfl_xor_sync(0xffffffffu, ss, o);
        sd += __shfl_xor_sync(0xffffffffu, sd, o);
    }
    if (lane == 0) { es[gw] = ss; ed[gw] = sd; }
}

// ------------------------- GAT2 aggregation, float4 -------------------------
__global__ void gat_agg(const float* __restrict__ h, const float* __restrict__ es,
                        const float* __restrict__ ed, const int* __restrict__ srcA,
                        const float* __restrict__ bias, float* __restrict__ out,
                        int Hh, int Fo, int elu)
{
    int gw = (blockIdx.x * blockDim.x + threadIdx.x) >> 5;
    int lane = threadIdx.x & 31;
    if (gw >= cBN * Hh) return;
    int hh = gw % Hh;
    int bn = gw / Hh;
    int b = bn / cN, n = bn % cN;
    int o0 = g_off[n];
    int deg = g_off[n + 1] - o0;
    if (deg > 4) deg = 4;
    int ssrc[4];
    float w[4];
    float edv = ed[(size_t)bn * Hh + hh];
    float mx = -1e30f;
    for (int j = 0; j < deg; j++) {
        int s = srcA[g_lst[o0 + j]];
        ssrc[j] = s;
        float l = es[((size_t)b * cN + s) * Hh + hh] + edv;
        l = l > 0.f ? l : 0.2f * l;
        w[j] = l;
        mx = fmaxf(mx, l);
    }
    float sum = 0.f;
    for (int j = 0; j < deg; j++) { w[j] = expf(w[j] - mx); sum += w[j]; }
    float inv = 1.f / sum;
    for (int f0 = lane * 4; f0 < Fo; f0 += 128) {
        float4 acc = make_float4(0.f, 0.f, 0.f, 0.f);
        for (int j = 0; j < deg; j++) {
            float4 hv = *(const float4*)(h + (((size_t)b * cN + ssrc[j]) * Hh + hh) * Fo + f0);
            float wj = w[j];
            acc.x = fmaf(wj, hv.x, acc.x); acc.y = fmaf(wj, hv.y, acc.y);
            acc.z = fmaf(wj, hv.z, acc.z); acc.w = fmaf(wj, hv.w, acc.w);
        }
        float4 bi = *(const float4*)(bias + hh * Fo + f0);
        float4 v;
        v.x = acc.x * inv + bi.x; v.y = acc.y * inv + bi.y;
        v.z = acc.z * inv + bi.z; v.w = acc.w * inv + bi.w;
        if (elu) {
            v.x = v.x > 0.f ? v.x : (expf(v.x) - 1.f);
            v.y = v.y > 0.f ? v.y : (expf(v.y) - 1.f);
            v.z = v.z > 0.f ? v.z : (expf(v.z) - 1.f);
            v.w = v.w > 0.f ? v.w : (expf(v.w) - 1.f);
        }
        *(float4*)(out + (size_t)gw * Fo + f0) = v;
    }
}

// ------------------------- cluster LSTM v3: 512 threads, 16-way k-split, pre prefetch -------
// thread = (hi 0..31, kc 0..15): w[4][16] regs; 4-round butterfly (in-warp);
// gate threads kc<4 own batch=kc. pre[t+1] prefetched into regs during step t's matmul.
// 224-thread vectorized DSMEM push + one CLUSTER_SYNC per step.
__global__ void __cluster_dims__(8, 1, 1) __launch_bounds__(512, 1)
lstm_cluster(const float* __restrict__ pre, const float* __restrict__ WhhT,
             float* __restrict__ hseq)
{
    __shared__ float hbuf[2][BPC][256];
    const int tid = threadIdx.x;
    const int hi = tid >> 4;        // 0..31
    const int kc = tid & 15;        // 0..15
    unsigned rank;
    asm("mov.u32 %0, %%cluster_ctarank;" : "=r"(rank));
    const int b0 = (blockIdx.x >> 3) * BPC;
    const int hg = (int)rank * 32 + hi;

    float w[4][16];
#pragma unroll
    for (int g = 0; g < 4; g++)
#pragma unroll
        for (int k = 0; k < 16; k++)
            w[g][k] = WhhT[(size_t)(kc * 16 + k) * 1024 + g * 256 + hg];

    for (int i = tid; i < 2 * BPC * 256; i += 512)
        ((float*)hbuf)[i] = 0.f;

    float cst = 0.f;
    const unsigned hb_base = smem_u32(hbuf);

    // cooperative push assignment: tid in [0,224) pushes one float4 to one peer
    const int pi = tid >> 5;
    const int pl = tid & 31;
    const int pbch = pl >> 3;
    const int pseg = pl & 7;
    int peer = (pi >= (int)rank) ? pi + 1 : pi;
    const bool doPush = (pi < 7);
    const unsigned pushOffBase = (unsigned)(((pbch) * 256 + (int)rank * 32 + pseg * 4) * 4);

    // prefetch pre for t=0 (gate threads kc<4 own batch=kc)
    float pg0 = 0.f, pg1 = 0.f, pg2 = 0.f, pg3 = 0.f;
    if (kc < BPC) {
        const float* pr = pre + ((size_t)((b0 + kc) * cN)) * 1024 + hg;
        pg0 = pr[0]; pg1 = pr[256]; pg2 = pr[512]; pg3 = pr[768];
    }

    CLUSTER_SYNC();

    for (int t = 0; t < cN; t++) {
        const int pb = t & 1;
        // kick off prefetch of pre[t+1] NOW (independent of hbuf); consumed next step
        float ng0 = 0.f, ng1 = 0.f, ng2 = 0.f, ng3 = 0.f;
        if (kc < BPC && t + 1 < cN) {
            const float* pr = pre + ((size_t)((b0 + kc) * cN + t + 1)) * 1024 + hg;
            ng0 = pr[0]; ng1 = pr[256]; ng2 = pr[512]; ng3 = pr[768];
        }

        float acc[4][BPC];
#pragma unroll
        for (int g = 0; g < 4; g++)
#pragma unroll
            for (int b = 0; b < BPC; b++) acc[g][b] = 0.f;

#pragma unroll
        for (int b = 0; b < BPC; b++) {
            const float* hp = &hbuf[pb][b][kc * 16];
#pragma unroll
            for (int k = 0; k < 16; k += 4) {
                float4 h4 = *(const float4*)(hp + k);
#pragma unroll
                for (int g = 0; g < 4; g++) {
                    acc[g][b] = fmaf(h4.x, w[g][k + 0], acc[g][b]);
                    acc[g][b] = fmaf(h4.y, w[g][k + 1], acc[g][b]);
                    acc[g][b] = fmaf(h4.z, w[g][k + 2], acc[g][b]);
                    acc[g][b] = fmaf(h4.w, w[g][k + 3], acc[g][b]);
                }
            }
        }

        // butterfly allreduce over the 16 k-chunks (in-warp: lane covers 2 hi x 16 kc)
#pragma unroll
        for (int o = 1; o < 16; o <<= 1)
#pragma unroll
            for (int g = 0; g < 4; g++)
#pragma unroll
                for (int b = 0; b < BPC; b++)
                    acc[g][b] += __shfl_xor_sync(0xffffffffu, acc[g][b], o);

        if (kc < BPC) {
            const int b = kc;
            float iv = acc[0][b] + pg0;
            float fv = acc[1][b] + pg1;
            float gv = acc[2][b] + pg2;
            float ov = acc[3][b] + pg3;
            float ig = 1.f / (1.f + __expf(-iv));
            float fg = 1.f / (1.f + __expf(-fv));
            float og = 1.f / (1.f + __expf(-ov));
            cst = fg * cst + ig * tanhf(gv);
            float hval = og * tanhf(cst);
            hseq[((size_t)((b0 + b) * cN + t)) * 256 + hg] = hval;
            hbuf[1 - pb][b][hg] = hval;         // local write
        }
        pg0 = ng0; pg1 = ng1; pg2 = ng2; pg3 = ng3;
        __syncthreads();

        if (doPush) {
            const unsigned off = (unsigned)((1 - pb) * BPC * 256 * 4) + pushOffBase;
            float4 v = *(const float4*)((const char*)hbuf + off);
            asm volatile(
                "{ .reg .b32 ra; mapa.shared::cluster.u32 ra, %0, %1; "
                "st.shared::cluster.v4.f32 [ra], {%2, %3, %4, %5}; }"
                :: "r"(hb_base + off), "r"(peer),
                   "f"(v.x), "f"(v.y), "f"(v.z), "f"(v.w)
                : "memory");
        }
        CLUSTER_SYNC();
    }
}

// ------------------------- output head, float4 -------------------------
__global__ void out_kernel(const int* __restrict__ qn, const int* __restrict__ pn,
                           const float* __restrict__ Wout, const float* __restrict__ b_out,
                           const float* __restrict__ hseq, const float* __restrict__ outp,
                           const float* __restrict__ outq, float* __restrict__ y)
{
    int gw = (blockIdx.x * blockDim.x + threadIdx.x) >> 5;
    int lane = threadIdx.x & 31;
    if (gw >= cBN) return;
    const float* hp = hseq + (size_t)gw * 256;
    float acc = 0.f;
#pragma unroll
    for (int f0 = lane * 4; f0 < 256; f0 += 128) {
        float4 hv = *(const float4*)(hp + f0);
        float4 wv = *(const float4*)(Wout + f0);
        acc = fmaf(hv.x, wv.x, acc); acc = fmaf(hv.y, wv.y, acc);
        acc = fmaf(hv.z, wv.z, acc); acc = fmaf(hv.w, wv.w, acc);
    }
    for (int o = 16; o; o >>= 1) acc += __shfl_xor_sync(0xffffffffu, acc, o);
    if (lane == 0) {
        float v = acc + outq[qn[gw]] + outp[pn[gw]] + b_out[0];
        y[gw] = 1.f / (1.f + expf(-v));
    }
}

// ------------------------- host orchestration -------------------------
static inline dim3 tg(int M, int N) { return dim3(N / 128, (M + 127) / 128); }

extern "C" void kernel_launch(void* const* d_in, const int* in_sizes, int n_in,
                              void* d_out, int out_size)
{
    const int*   p       = (const int*)d_in[1];
    const int*   q       = (const int*)d_in[2];
    const int*   r       = (const int*)d_in[3];
    const int*   aff     = (const int*)d_in[4];
    const int*   q_next  = (const int*)d_in[5];
    const int*   p_next  = (const int*)d_in[6];
    const int*   src     = (const int*)d_in[7];
    const int*   dst     = (const int*)d_in[8];
    const float* emb_p   = (const float*)d_in[9];
    const float* emb_q   = (const float*)d_in[10];
    const float* emb_r   = (const float*)d_in[11];
    const float* emb_aff = (const float*)d_in[12];
    const float* W_affcat= (const float*)d_in[13];
    const float* b_affcat= (const float*)d_in[14];
    const float* W_g1    = (const float*)d_in[15];
    const float* a_src1  = (const float*)d_in[16];
    const float* a_dst1  = (const float*)d_in[17];
    const float* b_g1    = (const float*)d_in[18];
    const float* W_g2    = (const float*)d_in[19];
    const float* a_src2  = (const float*)d_in[20];
    const float* a_dst2  = (const float*)d_in[21];
    const float* b_g2    = (const float*)d_in[22];
    const float* W_ih    = (const float*)d_in[23];
    const float* W_hh    = (const float*)d_in[24];
    const float* b_ih    = (const float*)d_in[25];
    const float* b_hh    = (const float*)d_in[26];
    const float* W_out   = (const float*)d_in[27];
    const float* b_out   = (const float*)d_in[28];
    int E = in_sizes[7];

    float *WhhT, *Wg1T, *WaT, *Wg2T, *WcT, *c1, *Pp1, *Pa1, *Pih_p, *Pih_q, *Pih_r;
    float *Ssp, *Sdp, *Ssa, *Sda, *cs1, *bsum;
    float *big1, *x1, *h2, *x2, *es1, *ed1, *es2, *ed2, *hseq, *outp, *outq;
    cudaGetSymbolAddress((void**)&WhhT,  g_WhhT);
    cudaGetSymbolAddress((void**)&Wg1T,  g_Wg1T);
    cudaGetSymbolAddress((void**)&WaT,   g_WaT);
    cudaGetSymbolAddress((void**)&Wg2T,  g_Wg2T);
    cudaGetSymbolAddress((void**)&WcT,   g_WcT);
    cudaGetSymbolAddress((void**)&c1,    g_c1);
    cudaGetSymbolAddress((void**)&Pp1,   g_Pp1);
    cudaGetSymbolAddress((void**)&Pa1,   g_Pa1);
    cudaGetSymbolAddress((void**)&Pih_p, g_Pih_p);
    cudaGetSymbolAddress((void**)&Pih_q, g_Pih_q);
    cudaGetSymbolAddress((void**)&Pih_r, g_Pih_r);
    cudaGetSymbolAddress((void**)&Ssp,   g_Ssp);
    cudaGetSymbolAddress((void**)&Sdp,   g_Sdp);
    cudaGetSymbolAddress((void**)&Ssa,   g_Ssa);
    cudaGetSymbolAddress((void**)&Sda,   g_Sda);
    cudaGetSymbolAddress((void**)&cs1,   g_cs1);
    cudaGetSymbolAddress((void**)&bsum,  g_bsum);
    cudaGetSymbolAddress((void**)&big1,  g_big1);
    cudaGetSymbolAddress((void**)&x1,    g_x1);
    cudaGetSymbolAddress((void**)&h2,    g_h2);
    cudaGetSymbolAddress((void**)&x2,    g_x2);
    cudaGetSymbolAddress((void**)&es1,   g_es1);
    cudaGetSymbolAddress((void**)&ed1,   g_ed1);
    cudaGetSymbolAddress((void**)&es2,   g_es2);
    cudaGetSymbolAddress((void**)&ed2,   g_ed2);
    cudaGetSymbolAddress((void**)&hseq,  g_hseq);
    cudaGetSymbolAddress((void**)&outp,  g_outp);
    cudaGetSymbolAddress((void**)&outq,  g_outq);

    cudaFuncSetAttribute(tgemm, cudaFuncAttributeMaxDynamicSharedMemorySize, TG_SMEM);
    cudaFuncSetAttribute(tgemm_pre, cudaFuncAttributeMaxDynamicSharedMemorySize, TG_SMEM);

    // --- dependency-free launches first ---
    rowdot_kernel<<<(NP*32 + 255)/256, 256>>>(emb_p, W_out + 512, outp, NP);   // 1
    rowdot_kernel<<<(NQ*32 + 255)/256, 256>>>(emb_q, W_out + 256, outq, NQ);   // 2
    tgemm<<<tg(NP, 1024), 256, TG_SMEM>>>(emb_p, 256, W_ih,       1024, Pih_p, 1024, NP, 1024, 256, 0); // 3
    tgemm<<<tg(NQ, 1024), 256, TG_SMEM>>>(emb_q, 256, W_ih + 256, 1024, Pih_q, 1024, NQ, 1024, 256, 0); // 4
    tgemm<<<tg(2,  1024), 256, TG_SMEM>>>(emb_r, 256, W_ih + 512, 1024, Pih_r, 1024, 2,  1024, 256, 0); // 5
    csr_build<<<1, 512>>>(dst, E);                                             // 6

    // --- weight preprocessing (small) ---
    transpose_k<<<(1024*256)/256, 256>>>(W_hh, WhhT, 1024, 256);
    transpose_k<<<(256*1024)/256, 256>>>(W_g1, Wg1T, 256, 1024);
    transpose_k<<<(512*256)/256,  256>>>(W_affcat, WaT, 512, 256);
    transpose_k<<<(1024*256)/256, 256>>>(W_g2, Wg2T, 1024, 256);

    sgemm_t<<<dim3(8, 4), 256>>>(Wg1T, WaT, WcT, 1024, 256, 512, 0);
    vecmat_k<<<4, 256>>>(b_affcat, W_g1, c1, 256, 1024);
    bsum_k<<<1, 1024>>>(b_ih, b_hh, bsum);

    // --- remaining per-table pre-projections (tf32 tensor cores) ---
    tgemm<<<tg(NP, 1024), 256, TG_SMEM>>>(emb_p,   256, WcT,       512, Pp1, 1024, NP, 1024, 256, 0);
    tgemm<<<tg(NA, 1024), 256, TG_SMEM>>>(emb_aff, 256, WcT + 256, 512, Pa1, 1024, NA, 1024, 256, 0);

    // per-table attention score tables
    score_tab<<<NP, 256>>>(Pp1, a_src1, a_dst1, Ssp, Sdp);
    score_tab<<<NA, 256>>>(Pa1, a_src1, a_dst1, Ssa, Sda);
    cvec_k<<<1, 512>>>(c1, a_src1, a_dst1, cs1);

    // --- GAT layer 1: logits + fused aggregation straight from tables ---
    scores_gather<<<(cBN*8 + 255)/256, 256>>>(p, aff, Ssp, Ssa, Sdp, Sda, cs1, es1, ed1);
    gat1_agg_fused<<<(cBN*32 + 255)/256, 256>>>(p, aff, es1, ed1, src, Pp1, Pa1, c1, b_g1, x1);

    // --- GAT layer 2 ---
    tgemm<<<tg(cBN, 256), 256, TG_SMEM>>>(x1, 1024, Wg2T, 1024, h2, 256, cBN, 256, 1024, 0);
    scores_kernel<<<(cBN*32)/256, 256>>>(h2, a_src2, a_dst2, es2, ed2, 1, 256);
    gat_agg<<<(cBN*32)/256, 256>>>(h2, es2, ed2, src, b_g2, x2, 1, 256, 0);

    // --- LSTM input: GEMM with fused gather-epilogue ---
    tgemm_pre<<<tg(cBN, 1024), 256, TG_SMEM>>>(x2, 256, W_ih + 768, 1024, big1, 1024,
                                               cBN, 1024, 256,
                                               p, q, r, Pih_p, Pih_q, Pih_r, bsum);

    // --- LSTM recurrence (512 threads, prefetched pre, vectorized DSMEM exchange) ---
    lstm_cluster<<<128, 512>>>(big1, WhhT, hseq);

    // --- output head ---
    out_kernel<<<(cBN*32)/256, 256>>>(q_next, p_next, W_out, b_out, hseq, outp, outq,
                                      (float*)d_out);
}

// round 17
// speedup vs baseline: 4.9185x; 1.9279x over previous
#include <cuda_runtime.h>
#include <math.h>

// Problem constants (fixed by the dataset)
#define cB 64
#define cN 499
#define cBN (cB*cN)          // 31936 tokens
#define NP 10001
#define NQ 2001
#define NA 11

#define BPC 4                // batches per cluster (16 clusters x 8 CTAs x BPC = 64)
#define BKK 16               // FFMA GEMM k-tile
#define TG_STAGE 18432       // tf32 GEMM: bytes per smem stage (128 rows x 36 floats)
#define TG_SMEM  73728       // 2 ops x 2 stages x 18432

// ------------------------- device scratch (no cudaMalloc allowed) -------------------------
__device__ __align__(16) float g_WhhT[256*1024];      // W_hh transposed: [k][gate]
__device__ __align__(16) float g_Wg1T[1024*256];      // W_g1^T  [n][o]
__device__ __align__(16) float g_WaT [256*512];       // W_affcat^T [o][i]
__device__ __align__(16) float g_Wg2T[256*1024];      // W_g2^T  [n][k]
__device__ __align__(16) float g_WcT [1024*512];      // (W_affcat @ W_g1)^T : [n][i]
__device__ __align__(16) float g_c1[1024];            // b_affcat @ W_g1
__device__ __align__(16) float g_Pp1[(size_t)NP*1024];   // emb_p @ Wc_p
__device__ __align__(16) float g_Pa1[NA*1024];           // emb_aff @ Wc_aff
__device__ __align__(16) float g_Pih_p[(size_t)NP*1024]; // emb_p @ W_ihT[0:256]
__device__ __align__(16) float g_Pih_q[(size_t)NQ*1024]; // emb_q @ W_ihT[256:512]
__device__ __align__(16) float g_Pih_r[2*1024];          // emb_r @ W_ihT[512:768]
__device__ __align__(16) float g_Ssp[NP*8];           // Pp1 . a_src1 (per head)
__device__ __align__(16) float g_Sdp[NP*8];           // Pp1 . a_dst1
__device__ __align__(16) float g_Ssa[NA*8];           // Pa1 . a_src1
__device__ __align__(16) float g_Sda[NA*8];           // Pa1 . a_dst1
__device__ __align__(16) float g_cs1[16];             // c1.a_src1 per head, then c1.a_dst1
__device__ __align__(16) float g_bsum[1024];          // b_ih + b_hh
__device__ __align__(16) float g_outp[NP];            // emb_p . W_out[512:768]
__device__ __align__(16) float g_outq[NQ];            // emb_q . W_out[256:512]
__device__ __align__(16) float g_big1[(size_t)cBN*1024];  // lstm_pre
__device__ __align__(16) float g_x1[(size_t)cBN*1024];
__device__ __align__(16) float g_h2[cBN*256];
__device__ __align__(16) float g_x2[cBN*256];
__device__ __align__(16) float g_es1[cBN*8];
__device__ __align__(16) float g_ed1[cBN*8];
__device__ __align__(16) float g_es2[cBN];
__device__ __align__(16) float g_ed2[cBN];
__device__ __align__(16) float g_hseq[cBN*256];
__device__ int g_off[cN+1];
__device__ int g_lst[4096];

// ------------------------- small helpers -------------------------
__device__ __forceinline__ unsigned smem_u32(const void* p) {
    unsigned a;
    asm("{ .reg .u64 t; cvta.to.shared.u64 t, %1; cvt.u32.u64 %0, t; }" : "=r"(a) : "l"(p));
    return a;
}
__device__ __forceinline__ void cpa16(unsigned dst, const void* src) {
    asm volatile("cp.async.ca.shared.global [%0], [%1], 16;" :: "r"(dst), "l"(src));
}
__device__ __forceinline__ void cpa16z(unsigned dst, const void* src, int n) {
    asm volatile("cp.async.ca.shared.global [%0], [%1], 16, %2;" :: "r"(dst), "l"(src), "r"(n));
}
#define CPA_COMMIT() asm volatile("cp.async.commit_group;" ::: "memory")
#define CLUSTER_SYNC() do { \
    asm volatile("barrier.cluster.arrive.aligned;" ::: "memory"); \
    asm volatile("barrier.cluster.wait.aligned;"   ::: "memory"); } while (0)

__device__ __forceinline__ void ldsm4(unsigned addr, unsigned* r) {
    asm volatile("ldmatrix.sync.aligned.m8n8.x4.shared.b16 {%0,%1,%2,%3}, [%4];"
                 : "=r"(r[0]), "=r"(r[1]), "=r"(r[2]), "=r"(r[3]) : "r"(addr));
}
__device__ __forceinline__ void ldsm2(unsigned addr, unsigned* r) {
    asm volatile("ldmatrix.sync.aligned.m8n8.x2.shared.b16 {%0,%1}, [%2];"
                 : "=r"(r[0]), "=r"(r[1]) : "r"(addr));
}
__device__ __forceinline__ unsigned f2tf(unsigned x) {
    unsigned y;
    asm("cvt.rna.tf32.f32 %0, %1;" : "=r"(y) : "r"(x));
    return y;
}
__device__ __forceinline__ void mma8(float* d, const unsigned* a, const unsigned* b) {
    asm volatile("mma.sync.aligned.m16n8k8.row.col.f32.tf32.tf32.f32 "
                 "{%0,%1,%2,%3}, {%4,%5,%6,%7}, {%8,%9}, {%0,%1,%2,%3};"
                 : "+f"(d[0]), "+f"(d[1]), "+f"(d[2]), "+f"(d[3])
                 : "r"(a[0]), "r"(a[1]), "r"(a[2]), "r"(a[3]), "r"(b[0]), "r"(b[1]));
}

// ------------------------- generic transpose -------------------------
__global__ void transpose_k(const float* __restrict__ in, float* __restrict__ out, int R, int C)
{
    int idx = blockIdx.x * blockDim.x + threadIdx.x;
    if (idx >= R * C) return;
    int c = idx / R;
    int r = idx - c * R;
    out[idx] = in[r * C + c];
}

// ------------------------- tf32 tensor-core GEMM core -------------------------
struct TGAcc { float a[4][4][4]; };

__device__ __forceinline__ void tgemm_main(const float* __restrict__ A, int lda,
                                           const float* __restrict__ Bn, int ldbn,
                                           int M, int K, int m0, int n0, TGAcc& AC)
{
    extern __shared__ float dynsm[];
    const unsigned smb = smem_u32(dynsm);
    const int tid = threadIdx.x, lane = tid & 31, wid = tid >> 5;
    const int wm = wid & 1, wn = wid >> 1;

    unsigned dOff[4];
    const float* sA[4];
    const float* sB[4];
    int vA[4];
#pragma unroll
    for (int i = 0; i < 4; i++) {
        int qd = tid + 256 * i;
        int row = qd >> 3, kq = qd & 7;
        dOff[i] = row * 144 + kq * 16;
        int ra = m0 + row;
        vA[i] = (ra < M) ? 16 : 0;
        sA[i] = A + (size_t)(vA[i] ? ra : 0) * lda + kq * 4;
        sB[i] = Bn + (size_t)(n0 + row) * ldbn + kq * 4;
    }

#pragma unroll
    for (int mt = 0; mt < 4; mt++)
#pragma unroll
        for (int nt = 0; nt < 4; nt++)
#pragma unroll
            for (int j = 0; j < 4; j++) AC.a[mt][nt][j] = 0.f;

#pragma unroll
    for (int i = 0; i < 4; i++) {
        cpa16z(smb + dOff[i], sA[i], vA[i]);
        cpa16z(smb + 2 * TG_STAGE + dOff[i], sB[i], 16);
    }
    CPA_COMMIT();

    const int aRowOff = wm * 64 + (lane & 7) + ((lane >> 3) & 1) * 8;
    const int aColB = (lane >> 4) * 16;
    const int bRowOff = wn * 32 + (lane & 7);
    const int bColB = ((lane >> 3) & 1) * 16;

    const int nst = K / 32;
    for (int st = 0; st < nst; st++) {
        const int buf = st & 1;
        if (st + 1 < nst) {
            const int k0 = (st + 1) * 32;
            const unsigned nb = (buf ^ 1) * TG_STAGE;
#pragma unroll
            for (int i = 0; i < 4; i++) {
                cpa16z(smb + nb + dOff[i], sA[i] + k0, vA[i]);
                cpa16z(smb + 2 * TG_STAGE + nb + dOff[i], sB[i] + k0, 16);
            }
            CPA_COMMIT();
            asm volatile("cp.async.wait_group 1;" ::: "memory");
        } else {
            asm volatile("cp.async.wait_group 0;" ::: "memory");
        }
        __syncthreads();
        const unsigned ab = smb + buf * TG_STAGE;
        const unsigned bb = smb + 2 * TG_STAGE + buf * TG_STAGE;
#pragma unroll
        for (int ks = 0; ks < 4; ks++) {
            unsigned af[4][4], bf[4][2];
#pragma unroll
            for (int mt = 0; mt < 4; mt++) {
                ldsm4(ab + (unsigned)((aRowOff + mt * 16) * 144 + aColB + ks * 32), af[mt]);
                af[mt][0] = f2tf(af[mt][0]); af[mt][1] = f2tf(af[mt][1]);
                af[mt][2] = f2tf(af[mt][2]); af[mt][3] = f2tf(af[mt][3]);
            }
#pragma unroll
            for (int nt = 0; nt < 4; nt++) {
                ldsm2(bb + (unsigned)((bRowOff + nt * 8) * 144 + bColB + ks * 32), bf[nt]);
                bf[nt][0] = f2tf(bf[nt][0]); bf[nt][1] = f2tf(bf[nt][1]);
            }
#pragma unroll
            for (int mt = 0; mt < 4; mt++)
#pragma unroll
                for (int nt = 0; nt < 4; nt++)
                    mma8(AC.a[mt][nt], af[mt], bf[nt]);
        }
        __syncthreads();
    }
}

// plain variant — 2 CTAs/SM
__global__ __launch_bounds__(256, 2) void tgemm(const float* __restrict__ A, int lda,
                                                const float* __restrict__ Bn, int ldbn,
                                                float* __restrict__ C, int ldc,
                                                int M, int N, int K, int accum)
{
    const int lane = threadIdx.x & 31, wid = threadIdx.x >> 5;
    const int wm = wid & 1, wn = wid >> 1;
    const int m0 = blockIdx.y * 128, n0 = blockIdx.x * 128;
    TGAcc AC;
    tgemm_main(A, lda, Bn, ldbn, M, K, m0, n0, AC);

    const int g = lane >> 2, c2 = (lane & 3) * 2;
#pragma unroll
    for (int mt = 0; mt < 4; mt++) {
        int r0 = m0 + wm * 64 + mt * 16 + g;
#pragma unroll
        for (int nt = 0; nt < 4; nt++) {
            int col = n0 + wn * 32 + nt * 8 + c2;
            if (r0 < M) {
                float2* pp = (float2*)(C + (size_t)r0 * ldc + col);
                float2 v = make_float2(AC.a[mt][nt][0], AC.a[mt][nt][1]);
                if (accum) { float2 o = *pp; v.x += o.x; v.y += o.y; }
                *pp = v;
            }
            if (r0 + 8 < M) {
                float2* pp = (float2*)(C + (size_t)(r0 + 8) * ldc + col);
                float2 v = make_float2(AC.a[mt][nt][2], AC.a[mt][nt][3]);
                if (accum) { float2 o = *pp; v.x += o.x; v.y += o.y; }
                *pp = v;
            }
        }
    }
}

// fused-epilogue variant: C = A@B + Tp[fp[m]] + Tq[fq[m]] + Tr[fr[m]] + bsum  (lstm pre)
__global__ __launch_bounds__(256, 2) void tgemm_pre(const float* __restrict__ A, int lda,
                                                    const float* __restrict__ Bn, int ldbn,
                                                    float* __restrict__ C, int ldc,
                                                    int M, int N, int K,
                                                    const int* __restrict__ fp,
                                                    const int* __restrict__ fq,
                                                    const int* __restrict__ fr,
                                                    const float* __restrict__ Tp,
                                                    const float* __restrict__ Tq,
                                                    const float* __restrict__ Tr,
                                                    const float* __restrict__ bsum)
{
    const int lane = threadIdx.x & 31, wid = threadIdx.x >> 5;
    const int wm = wid & 1, wn = wid >> 1;
    const int m0 = blockIdx.y * 128, n0 = blockIdx.x * 128;
    TGAcc AC;
    tgemm_main(A, lda, Bn, ldbn, M, K, m0, n0, AC);

    const int g = lane >> 2, c2 = (lane & 3) * 2;
#pragma unroll
    for (int mt = 0; mt < 4; mt++) {
        int r0 = m0 + wm * 64 + mt * 16 + g;
        bool ok0 = r0 < M, ok1 = (r0 + 8) < M;
        size_t p0 = 0, q0 = 0, rr0 = 0, p1 = 0, q1 = 0, rr1 = 0;
        if (ok0) { p0 = (size_t)fp[r0] * 1024; q0 = (size_t)fq[r0] * 1024; rr0 = (size_t)fr[r0] * 1024; }
        if (ok1) { p1 = (size_t)fp[r0+8] * 1024; q1 = (size_t)fq[r0+8] * 1024; rr1 = (size_t)fr[r0+8] * 1024; }
#pragma unroll
        for (int nt = 0; nt < 4; nt++) {
            int col = n0 + wn * 32 + nt * 8 + c2;
            float2 bs = *(const float2*)(bsum + col);
            if (ok0) {
                float2 tp = *(const float2*)(Tp + p0 + col);
                float2 tq = *(const float2*)(Tq + q0 + col);
                float2 tr = *(const float2*)(Tr + rr0 + col);
                float2 v = make_float2(AC.a[mt][nt][0] + tp.x + tq.x + tr.x + bs.x,
                                       AC.a[mt][nt][1] + tp.y + tq.y + tr.y + bs.y);
                *(float2*)(C + (size_t)r0 * ldc + col) = v;
            }
            if (ok1) {
                float2 tp = *(const float2*)(Tp + p1 + col);
                float2 tq = *(const float2*)(Tq + q1 + col);
                float2 tr = *(const float2*)(Tr + rr1 + col);
                float2 v = make_float2(AC.a[mt][nt][2] + tp.x + tq.x + tr.x + bs.x,
                                       AC.a[mt][nt][3] + tp.y + tq.y + tr.y + bs.y);
                *(float2*)(C + (size_t)(r0 + 8) * ldc + col) = v;
            }
        }
    }
}

// ------------------------- FFMA SGEMM (exact; Wc composition only) -------------------------
__global__ __launch_bounds__(256, 2) void sgemm_t(const float* __restrict__ A,
                                                  const float* __restrict__ Bm,
                                                  float* __restrict__ C,
                                                  int M, int K, int Nc, int accum)
{
    __shared__ float As[2][BKK][128];
    __shared__ float Bs[2][BKK][128];
    const int tid = threadIdx.x;
    const int m0 = blockIdx.x * 128, n0 = blockIdx.y * 128;
    const int tRow = (tid >> 4) * 8, tCol = (tid & 15) * 8;

    const int am0 = tid >> 2, ak = (tid & 3) * 4;
    const int am1 = am0 + 64;
    const int br0 = tid >> 5, bc = (tid & 31) * 4;
    const int br1 = br0 + 8;

    const bool v0 = (m0 + am0) < M, v1 = (m0 + am1) < M;
    const float* A0 = A + (size_t)(v0 ? m0 + am0 : 0) * K + ak;
    const float* A1 = A + (size_t)(v1 ? m0 + am1 : 0) * K + ak;
    const float* B0 = Bm + (size_t)br0 * Nc + n0 + bc;
    const float* B1 = Bm + (size_t)br1 * Nc + n0 + bc;

    unsigned sB00 = smem_u32(&Bs[0][br0][bc]), sB01 = smem_u32(&Bs[0][br1][bc]);
    unsigned sB10 = smem_u32(&Bs[1][br0][bc]), sB11 = smem_u32(&Bs[1][br1][bc]);

    float acc[8][8];
#pragma unroll
    for (int i = 0; i < 8; i++)
#pragma unroll
        for (int j = 0; j < 8; j++) acc[i][j] = 0.f;

    const float4 z4 = make_float4(0.f, 0.f, 0.f, 0.f);
    float4 a0 = v0 ? *(const float4*)A0 : z4;
    float4 a1 = v1 ? *(const float4*)A1 : z4;
    cpa16(sB00, B0);
    cpa16(sB01, B1);
    CPA_COMMIT();

    const int nt = K / BKK;
    for (int it = 0; it < nt; it++) {
        const int buf = it & 1;
        As[buf][ak + 0][am0] = a0.x; As[buf][ak + 1][am0] = a0.y;
        As[buf][ak + 2][am0] = a0.z; As[buf][ak + 3][am0] = a0.w;
        As[buf][ak + 0][am1] = a1.x; As[buf][ak + 1][am1] = a1.y;
        As[buf][ak + 2][am1] = a1.z; As[buf][ak + 3][am1] = a1.w;
        if (it + 1 < nt) {
            const int k0 = (it + 1) * BKK;
            a0 = v0 ? *(const float4*)(A0 + k0) : z4;
            a1 = v1 ? *(const float4*)(A1 + k0) : z4;
            cpa16(buf ? sB00 : sB10, B0 + (size_t)k0 * Nc);
            cpa16(buf ? sB01 : sB11, B1 + (size_t)k0 * Nc);
            CPA_COMMIT();
            asm volatile("cp.async.wait_group 1;" ::: "memory");
        } else {
            asm volatile("cp.async.wait_group 0;" ::: "memory");
        }
        __syncthreads();
#pragma unroll
        for (int kk = 0; kk < BKK; kk++) {
            float4 ra0 = *(const float4*)&As[buf][kk][tRow];
            float4 ra1 = *(const float4*)&As[buf][kk][tRow + 4];
            float4 rb0 = *(const float4*)&Bs[buf][kk][tCol];
            float4 rb1 = *(const float4*)&Bs[buf][kk][tCol + 4];
            float ra[8] = {ra0.x, ra0.y, ra0.z, ra0.w, ra1.x, ra1.y, ra1.z, ra1.w};
            float rb[8] = {rb0.x, rb0.y, rb0.z, rb0.w, rb1.x, rb1.y, rb1.z, rb1.w};
#pragma unroll
            for (int i = 0; i < 8; i++)
#pragma unroll
                for (int j = 0; j < 8; j++) acc[i][j] = fmaf(ra[i], rb[j], acc[i][j]);
        }
        __syncthreads();
    }

    for (int i = 0; i < 8; i++) {
        int m = m0 + tRow + i;
        if (m >= M) break;
        float* Crow = C + (size_t)m * Nc + n0 + tCol;
#pragma unroll
        for (int j = 0; j < 8; j += 4) {
            float4 v = make_float4(acc[i][j], acc[i][j+1], acc[i][j+2], acc[i][j+3]);
            if (accum) {
                float4 o = *(float4*)(Crow + j);
                v.x += o.x; v.y += o.y; v.z += o.z; v.w += o.w;
            }
            *(float4*)(Crow + j) = v;
        }
    }
}

// ------------------------- vec @ mat -------------------------
__global__ void vecmat_k(const float* __restrict__ v, const float* __restrict__ Wm,
                         float* __restrict__ out, int K, int Nc)
{
    int n = blockIdx.x * blockDim.x + threadIdx.x;
    if (n >= Nc) return;
    float acc = 0.f;
    for (int k = 0; k < K; k++) acc = fmaf(v[k], Wm[(size_t)k * Nc + n], acc);
    out[n] = acc;
}

// ------------------------- row dot (cols=256), float4 loads -------------------------
__global__ void rowdot_kernel(const float* __restrict__ emb, const float* __restrict__ w,
                              float* __restrict__ out, int rows)
{
    int gw = (blockIdx.x * blockDim.x + threadIdx.x) >> 5;
    int lane = threadIdx.x & 31;
    if (gw >= rows) return;
    const float* e = emb + (size_t)gw * 256;
    float acc = 0.f;
#pragma unroll
    for (int f0 = lane * 4; f0 < 256; f0 += 128) {
        float4 ev = *(const float4*)(e + f0);
        float4 wv = *(const float4*)(w + f0);
        acc = fmaf(ev.x, wv.x, acc); acc = fmaf(ev.y, wv.y, acc);
        acc = fmaf(ev.z, wv.z, acc); acc = fmaf(ev.w, wv.w, acc);
    }
    for (int o = 16; o; o >>= 1) acc += __shfl_xor_sync(0xffffffffu, acc, o);
    if (lane == 0) out[gw] = acc;
}

// ------------------------- per-table score tables (float4) -------------------------
__global__ void score_tab(const float* __restrict__ P, const float* __restrict__ a_s,
                          const float* __restrict__ a_d, float* __restrict__ Ss,
                          float* __restrict__ Sd)
{
    int row = blockIdx.x;
    int h = threadIdx.x >> 5;         // 8 warps = 8 heads
    int lane = threadIdx.x & 31;
    int f0 = h * 128 + lane * 4;
    float4 pv = *(const float4*)(P + (size_t)row * 1024 + f0);
    float4 as = *(const float4*)(a_s + f0);
    float4 ad = *(const float4*)(a_d + f0);
    float ss = pv.x * as.x + pv.y * as.y + pv.z * as.z + pv.w * as.w;
    float sd = pv.x * ad.x + pv.y * ad.y + pv.z * ad.z + pv.w * ad.w;
    for (int o = 16; o; o >>= 1) {
        ss += __shfl_xor_sync(0xffffffffu, ss, o);
        sd += __shfl_xor_sync(0xffffffffu, sd, o);
    }
    if (lane == 0) { Ss[row * 8 + h] = ss; Sd[row * 8 + h] = sd; }
}

// cs1[0..7] = c1.a_src per head, cs1[8..15] = c1.a_dst per head
__global__ void cvec_k(const float* __restrict__ c1, const float* __restrict__ a_s,
                       const float* __restrict__ a_d, float* __restrict__ cs)
{
    int w = threadIdx.x >> 5;         // 16 warps
    int lane = threadIdx.x & 31;
    int h = w & 7;
    const float* a = (w < 8) ? a_s : a_d;
    float acc = 0.f;
#pragma unroll
    for (int f = lane; f < 128; f += 32)
        acc = fmaf(c1[h * 128 + f], a[h * 128 + f], acc);
    for (int o = 16; o; o >>= 1) acc += __shfl_xor_sync(0xffffffffu, acc, o);
    if (lane == 0) cs[w] = acc;
}

__global__ void bsum_k(const float* __restrict__ a, const float* __restrict__ b,
                       float* __restrict__ o)
{
    int i = threadIdx.x;
    o[i] = a[i] + b[i];
}

// es1/ed1 gather
__global__ void scores_gather(const int* __restrict__ p, const int* __restrict__ aff,
                              const float* __restrict__ Ssp, const float* __restrict__ Ssa,
                              const float* __restrict__ Sdp, const float* __restrict__ Sda,
                              const float* __restrict__ cs, float* __restrict__ es,
                              float* __restrict__ ed)
{
    int idx = blockIdx.x * blockDim.x + threadIdx.x;
    if (idx >= cBN * 8) return;
    int bn = idx >> 3, h = idx & 7;
    int pv = p[bn], av = aff[bn];
    es[idx] = Ssp[pv * 8 + h] + Ssa[av * 8 + h] + cs[h];
    ed[idx] = Sdp[pv * 8 + h] + Sda[av * 8 + h] + cs[8 + h];
}

// ------------------------- deterministic CSR of incoming edges -------------------------
__global__ void csr_build(const int* __restrict__ dst, int E)
{
    __shared__ int cnt[cN];
    int tid = threadIdx.x;
    for (int n = tid; n < cN; n += blockDim.x) cnt[n] = 0;
    __syncthreads();
    for (int e = tid; e < E; e += blockDim.x) atomicAdd(&cnt[dst[e]], 1);
    __syncthreads();
    if (tid == 0) {
        int s = 0;
        for (int n = 0; n < cN; n++) { g_off[n] = s; s += cnt[n]; }
        g_off[cN] = s;
    }
    __syncthreads();
    for (int n = tid; n < cN; n += blockDim.x) cnt[n] = 0;
    __syncthreads();
    for (int e = tid; e < E; e += blockDim.x) {
        int d = dst[e];
        int pos = atomicAdd(&cnt[d], 1);
        g_lst[g_off[d] + pos] = e;
    }
    __syncthreads();
    for (int n = tid; n < cN; n += blockDim.x) {
        int o0 = g_off[n], o1 = g_off[n + 1];
        for (int i = o0 + 1; i < o1; i++) {
            int v = g_lst[i], j = i - 1;
            while (j >= o0 && g_lst[j] > v) { g_lst[j + 1] = g_lst[j]; j--; }
            g_lst[j + 1] = v;
        }
    }
}

// ------------------------- GAT1 fused aggregation: one WARP per destination node ----------
__global__ void gat1_agg_fused(const int* __restrict__ p, const int* __restrict__ aff,
                               const float* __restrict__ es, const float* __restrict__ ed,
                               const int* __restrict__ srcA,
                               const float* __restrict__ Pp1, const float* __restrict__ Pa1,
                               const float* __restrict__ c1, const float* __restrict__ bias,
                               float* __restrict__ out)
{
    int bn = (blockIdx.x * blockDim.x + threadIdx.x) >> 5;
    int lane = threadIdx.x & 31;
    if (bn >= cBN) return;
    int b = bn / cN, n = bn % cN;
    int o0 = g_off[n];
    int deg = g_off[n + 1] - o0;
    if (deg > 4) deg = 4;

    int ipj = 0, iaj = 0, bsj = 0;
    if (lane < deg) {
        int s = srcA[g_lst[o0 + lane]];
        bsj = b * cN + s;
        ipj = p[bsj];
        iaj = aff[bsj];
    }
    int ip[4], ia[4], bs[4];
#pragma unroll
    for (int j = 0; j < 4; j++) {
        ip[j] = __shfl_sync(0xffffffffu, ipj, j);
        ia[j] = __shfl_sync(0xffffffffu, iaj, j);
        bs[j] = __shfl_sync(0xffffffffu, bsj, j);
    }

    float w0 = 0.f, w1 = 0.f, w2 = 0.f, w3 = 0.f, winv = 1.f;
    if (lane < 8) {
        float edv = ed[bn * 8 + lane];
        float l[4];
        float mx = -1e30f;
        for (int j = 0; j < deg; j++) {
            float lv = es[bs[j] * 8 + lane] + edv;
            lv = lv > 0.f ? lv : 0.2f * lv;
            l[j] = lv;
            mx = fmaxf(mx, lv);
        }
        float sum = 0.f;
        for (int j = 0; j < deg; j++) { l[j] = expf(l[j] - mx); sum += l[j]; }
        w0 = l[0]; if (deg > 1) w1 = l[1]; if (deg > 2) w2 = l[2]; if (deg > 3) w3 = l[3];
        winv = 1.f / sum;
    }

    const size_t base = (size_t)bn * 1024;
#pragma unroll
    for (int c = 0; c < 8; c++) {
        float wj[4];
        wj[0] = __shfl_sync(0xffffffffu, w0, c);
        wj[1] = __shfl_sync(0xffffffffu, w1, c);
        wj[2] = __shfl_sync(0xffffffffu, w2, c);
        wj[3] = __shfl_sync(0xffffffffu, w3, c);
        float inv = __shfl_sync(0xffffffffu, winv, c);
        int fo = c * 128 + lane * 4;
        float4 acc = make_float4(0.f, 0.f, 0.f, 0.f);
        for (int j = 0; j < deg; j++) {
            float4 a = *(const float4*)(Pp1 + (size_t)ip[j] * 1024 + fo);
            float4 cc = *(const float4*)(Pa1 + (size_t)ia[j] * 1024 + fo);
            float ww = wj[j];
            acc.x = fmaf(ww, a.x + cc.x, acc.x);
            acc.y = fmaf(ww, a.y + cc.y, acc.y);
            acc.z = fmaf(ww, a.z + cc.z, acc.z);
            acc.w = fmaf(ww, a.w + cc.w, acc.w);
        }
        float4 cv = *(const float4*)(c1 + fo);
        float4 bi = *(const float4*)(bias + fo);
        float4 v;
        v.x = acc.x * inv + cv.x + bi.x;
        v.y = acc.y * inv + cv.y + bi.y;
        v.z = acc.z * inv + cv.z + bi.z;
        v.w = acc.w * inv + cv.w + bi.w;
        v.x = v.x > 0.f ? v.x : (expf(v.x) - 1.f);
        v.y = v.y > 0.f ? v.y : (expf(v.y) - 1.f);
        v.z = v.z > 0.f ? v.z : (expf(v.z) - 1.f);
        v.w = v.w > 0.f ? v.w : (expf(v.w) - 1.f);
        *(float4*)(out + base + fo) = v;
    }
}

// ------------------------- attention logits (GAT2), float4 -------------------------
__global__ void scores_kernel(const float* __restrict__ h, const float* __restrict__ a_s,
                              const float* __restrict__ a_d, float* __restrict__ es,
                              float* __restrict__ ed, int Hh, int Fo)
{
    int gw = (blockIdx.x * blockDim.x + threadIdx.x) >> 5;
    int lane = threadIdx.x & 31;
    if (gw >= cBN * Hh) return;
    int hh = gw % Hh;
    const float* hp = h + (size_t)gw * Fo;
    float ss = 0.f, sd = 0.f;
    for (int f0 = lane * 4; f0 < Fo; f0 += 128) {
        float4 hv = *(const float4*)(hp + f0);
        float4 as = *(const float4*)(a_s + hh * Fo + f0);
        float4 ad = *(const float4*)(a_d + hh * Fo + f0);
        ss = fmaf(hv.x, as.x, ss); ss = fmaf(hv.y, as.y, ss);
        ss = fmaf(hv.z, as.z, ss); ss = fmaf(hv.w, as.w, ss);
        sd = fmaf(hv.x, ad.x, sd); sd = fmaf(hv.y, ad.y, sd);
        sd = fmaf(hv.z, ad.z, sd); sd = fmaf(hv.w, ad.w, sd);
    }
    for (int o = 16; o; o >>= 1) {
        ss += __shfl_xor_sync(0xffffffffu, ss, o);
        sd += __shfl_xor_sync(0xffffffffu, sd, o);
    }
    if (lane == 0) { es[gw] = ss; ed[gw] = sd; }
}

// ------------------------- GAT2 aggregation, float4 -------------------------
__global__ void gat_agg(const float* __restrict__ h, const float* __restrict__ es,
                        const float* __restrict__ ed, const int* __restrict__ srcA,
                        const float* __restrict__ bias, float* __restrict__ out,
                        int Hh, int Fo, int elu)
{
    int gw = (blockIdx.x * blockDim.x + threadIdx.x) >> 5;
    int lane = threadIdx.x & 31;
    if (gw >= cBN * Hh) return;
    int hh = gw % Hh;
    int bn = gw / Hh;
    int b = bn / cN, n = bn % cN;
    int o0 = g_off[n];
    int deg = g_off[n + 1] - o0;
    if (deg > 4) deg = 4;
    int ssrc[4];
    float w[4];
    float edv = ed[(size_t)bn * Hh + hh];
    float mx = -1e30f;
    for (int j = 0; j < deg; j++) {
        int s = srcA[g_lst[o0 + j]];
        ssrc[j] = s;
        float l = es[((size_t)b * cN + s) * Hh + hh] + edv;
        l = l > 0.f ? l : 0.2f * l;
        w[j] = l;
        mx = fmaxf(mx, l);
    }
    float sum = 0.f;
    for (int j = 0; j < deg; j++) { w[j] = expf(w[j] - mx); sum += w[j]; }
    float inv = 1.f / sum;
    for (int f0 = lane * 4; f0 < Fo; f0 += 128) {
        float4 acc = make_float4(0.f, 0.f, 0.f, 0.f);
        for (int j = 0; j < deg; j++) {
            float4 hv = *(const float4*)(h + (((size_t)b * cN + ssrc[j]) * Hh + hh) * Fo + f0);
            float wj = w[j];
            acc.x = fmaf(wj, hv.x, acc.x); acc.y = fmaf(wj, hv.y, acc.y);
            acc.z = fmaf(wj, hv.z, acc.z); acc.w = fmaf(wj, hv.w, acc.w);
        }
        float4 bi = *(const float4*)(bias + hh * Fo + f0);
        float4 v;
        v.x = acc.x * inv + bi.x; v.y = acc.y * inv + bi.y;
        v.z = acc.z * inv + bi.z; v.w = acc.w * inv + bi.w;
        if (elu) {
            v.x = v.x > 0.f ? v.x : (expf(v.x) - 1.f);
            v.y = v.y > 0.f ? v.y : (expf(v.y) - 1.f);
            v.z = v.z > 0.f ? v.z : (expf(v.z) - 1.f);
            v.w = v.w > 0.f ? v.w : (expf(v.w) - 1.f);
        }
        *(float4*)(out + (size_t)gw * Fo + f0) = v;
    }
}

// ------------------------- cluster LSTM v4: conflict-free smem, warp=kc broadcast ----------
// thread = (warp=kc 0..15, lane=hi 0..31). hbuf matmul reads are warp-uniform (smem
// BROADCAST, zero bank conflicts). Partials reduced through part[g][b][kc][hi] (lanes
// contiguous -> conflict-free STS/LDS). 128 gate threads (b,hi) do the cell update.
// pre[t+1] register prefetch + 224-thread vectorized DSMEM push + one CLUSTER_SYNC/step.
__global__ void __cluster_dims__(8, 1, 1) __launch_bounds__(512, 1)
lstm_cluster(const float* __restrict__ pre, const float* __restrict__ WhhT,
             float* __restrict__ hseq)
{
    __shared__ float hbuf[2][BPC][256];
    __shared__ float part[4][BPC][16][32];   // [gate][batch][kc][hi]
    const int tid = threadIdx.x;
    const int kc = tid >> 5;        // warp id 0..15 = k chunk
    const int hi = tid & 31;        // lane = h index within CTA slice
    unsigned rank;
    asm("mov.u32 %0, %%cluster_ctarank;" : "=r"(rank));
    const int b0 = (blockIdx.x >> 3) * BPC;
    const int hg = (int)rank * 32 + hi;

    float w[4][16];
#pragma unroll
    for (int g = 0; g < 4; g++)
#pragma unroll
        for (int k = 0; k < 16; k++)
            w[g][k] = WhhT[(size_t)(kc * 16 + k) * 1024 + g * 256 + hg];

    for (int i = tid; i < 2 * BPC * 256; i += 512)
        ((float*)hbuf)[i] = 0.f;

    float cst = 0.f;
    const unsigned hb_base = smem_u32(hbuf);

    // cooperative push: tid in [0,224) pushes one float4 to one peer
    const int pi = tid >> 5;
    const int pl = tid & 31;
    const int pbch = pl >> 3;
    const int pseg = pl & 7;
    int peer = (pi >= (int)rank) ? pi + 1 : pi;
    const bool doPush = (pi < 7);
    const unsigned pushOffBase = (unsigned)(((pbch) * 256 + (int)rank * 32 + pseg * 4) * 4);

    // gate threads: tid<128 -> (gb = tid>>5 batch, hi lane); own cell (b0+gb, hg)
    const int gb = tid >> 5;
    const bool isGate = (tid < 128);

    // prefetch pre for t=0
    float pg0 = 0.f, pg1 = 0.f, pg2 = 0.f, pg3 = 0.f;
    if (isGate) {
        const float* pr = pre + ((size_t)((b0 + gb) * cN)) * 1024 + hg;
        pg0 = pr[0]; pg1 = pr[256]; pg2 = pr[512]; pg3 = pr[768];
    }

    CLUSTER_SYNC();

    for (int t = 0; t < cN; t++) {
        const int pb = t & 1;
        // prefetch pre[t+1] (independent of hbuf)
        float ng0 = 0.f, ng1 = 0.f, ng2 = 0.f, ng3 = 0.f;
        if (isGate && t + 1 < cN) {
            const float* pr = pre + ((size_t)((b0 + gb) * cN + t + 1)) * 1024 + hg;
            ng0 = pr[0]; ng1 = pr[256]; ng2 = pr[512]; ng3 = pr[768];
        }

        float acc[4][BPC];
#pragma unroll
        for (int g = 0; g < 4; g++)
#pragma unroll
            for (int b = 0; b < BPC; b++) acc[g][b] = 0.f;

#pragma unroll
        for (int b = 0; b < BPC; b++) {
            const float* hp = &hbuf[pb][b][kc * 16];   // warp-uniform: broadcast reads
#pragma unroll
            for (int k = 0; k < 16; k += 4) {
                float4 h4 = *(const float4*)(hp + k);
#pragma unroll
                for (int g = 0; g < 4; g++) {
                    acc[g][b] = fmaf(h4.x, w[g][k + 0], acc[g][b]);
                    acc[g][b] = fmaf(h4.y, w[g][k + 1], acc[g][b]);
                    acc[g][b] = fmaf(h4.z, w[g][k + 2], acc[g][b]);
                    acc[g][b] = fmaf(h4.w, w[g][k + 3], acc[g][b]);
                }
            }
        }

        // store partials: lanes contiguous -> conflict-free
#pragma unroll
        for (int g = 0; g < 4; g++)
#pragma unroll
            for (int b = 0; b < BPC; b++)
                part[g][b][kc][hi] = acc[g][b];
        __syncthreads();

        if (isGate) {
            const int b = gb;
            float s0 = 0.f, s1 = 0.f, s2 = 0.f, s3 = 0.f;
#pragma unroll
            for (int k = 0; k < 16; k++) {
                s0 += part[0][b][k][hi];
                s1 += part[1][b][k][hi];
                s2 += part[2][b][k][hi];
                s3 += part[3][b][k][hi];
            }
            float iv = s0 + pg0;
            float fv = s1 + pg1;
            float gv = s2 + pg2;
            float ov = s3 + pg3;
            float ig = 1.f / (1.f + __expf(-iv));
            float fg = 1.f / (1.f + __expf(-fv));
            float og = 1.f / (1.f + __expf(-ov));
            cst = fg * cst + ig * tanhf(gv);
            float hval = og * tanhf(cst);
            hseq[((size_t)((b0 + b) * cN + t)) * 256 + hg] = hval;
            hbuf[1 - pb][b][hg] = hval;         // local write
        }
        pg0 = ng0; pg1 = ng1; pg2 = ng2; pg3 = ng3;
        __syncthreads();

        if (doPush) {
            const unsigned off = (unsigned)((1 - pb) * BPC * 256 * 4) + pushOffBase;
            float4 v = *(const float4*)((const char*)hbuf + off);
            asm volatile(
                "{ .reg .b32 ra; mapa.shared::cluster.u32 ra, %0, %1; "
                "st.shared::cluster.v4.f32 [ra], {%2, %3, %4, %5}; }"
                :: "r"(hb_base + off), "r"(peer),
                   "f"(v.x), "f"(v.y), "f"(v.z), "f"(v.w)
                : "memory");
        }
        CLUSTER_SYNC();
    }
}

// ------------------------- output head, float4 -------------------------
__global__ void out_kernel(const int* __restrict__ qn, const int* __restrict__ pn,
                           const float* __restrict__ Wout, const float* __restrict__ b_out,
                           const float* __restrict__ hseq, const float* __restrict__ outp,
                           const float* __restrict__ outq, float* __restrict__ y)
{
    int gw = (blockIdx.x * blockDim.x + threadIdx.x) >> 5;
    int lane = threadIdx.x & 31;
    if (gw >= cBN) return;
    const float* hp = hseq + (size_t)gw * 256;
    float acc = 0.f;
#pragma unroll
    for (int f0 = lane * 4; f0 < 256; f0 += 128) {
        float4 hv = *(const float4*)(hp + f0);
        float4 wv = *(const float4*)(Wout + f0);
        acc = fmaf(hv.x, wv.x, acc); acc = fmaf(hv.y, wv.y, acc);
        acc = fmaf(hv.z, wv.z, acc); acc = fmaf(hv.w, wv.w, acc);
    }
    for (int o = 16; o; o >>= 1) acc += __shfl_xor_sync(0xffffffffu, acc, o);
    if (lane == 0) {
        float v = acc + outq[qn[gw]] + outp[pn[gw]] + b_out[0];
        y[gw] = 1.f / (1.f + expf(-v));
    }
}

// ------------------------- host orchestration -------------------------
static inline dim3 tg(int M, int N) { return dim3(N / 128, (M + 127) / 128); }

extern "C" void kernel_launch(void* const* d_in, const int* in_sizes, int n_in,
                              void* d_out, int out_size)
{
    const int*   p       = (const int*)d_in[1];
    const int*   q       = (const int*)d_in[2];
    const int*   r       = (const int*)d_in[3];
    const int*   aff     = (const int*)d_in[4];
    const int*   q_next  = (const int*)d_in[5];
    const int*   p_next  = (const int*)d_in[6];
    const int*   src     = (const int*)d_in[7];
    const int*   dst     = (const int*)d_in[8];
    const float* emb_p   = (const float*)d_in[9];
    const float* emb_q   = (const float*)d_in[10];
    const float* emb_r   = (const float*)d_in[11];
    const float* emb_aff = (const float*)d_in[12];
    const float* W_affcat= (const float*)d_in[13];
    const float* b_affcat= (const float*)d_in[14];
    const float* W_g1    = (const float*)d_in[15];
    const float* a_src1  = (const float*)d_in[16];
    const float* a_dst1  = (const float*)d_in[17];
    const float* b_g1    = (const float*)d_in[18];
    const float* W_g2    = (const float*)d_in[19];
    const float* a_src2  = (const float*)d_in[20];
    const float* a_dst2  = (const float*)d_in[21];
    const float* b_g2    = (const float*)d_in[22];
    const float* W_ih    = (const float*)d_in[23];
    const float* W_hh    = (const float*)d_in[24];
    const float* b_ih    = (const float*)d_in[25];
    const float* b_hh    = (const float*)d_in[26];
    const float* W_out   = (const float*)d_in[27];
    const float* b_out   = (const float*)d_in[28];
    int E = in_sizes[7];

    float *WhhT, *Wg1T, *WaT, *Wg2T, *WcT, *c1, *Pp1, *Pa1, *Pih_p, *Pih_q, *Pih_r;
    float *Ssp, *Sdp, *Ssa, *Sda, *cs1, *bsum;
    float *big1, *x1, *h2, *x2, *es1, *ed1, *es2, *ed2, *hseq, *outp, *outq;
    cudaGetSymbolAddress((void**)&WhhT,  g_WhhT);
    cudaGetSymbolAddress((void**)&Wg1T,  g_Wg1T);
    cudaGetSymbolAddress((void**)&WaT,   g_WaT);
    cudaGetSymbolAddress((void**)&Wg2T,  g_Wg2T);
    cudaGetSymbolAddress((void**)&WcT,   g_WcT);
    cudaGetSymbolAddress((void**)&c1,    g_c1);
    cudaGetSymbolAddress((void**)&Pp1,   g_Pp1);
    cudaGetSymbolAddress((void**)&Pa1,   g_Pa1);
    cudaGetSymbolAddress((void**)&Pih_p, g_Pih_p);
    cudaGetSymbolAddress((void**)&Pih_q, g_Pih_q);
    cudaGetSymbolAddress((void**)&Pih_r, g_Pih_r);
    cudaGetSymbolAddress((void**)&Ssp,   g_Ssp);
    cudaGetSymbolAddress((void**)&Sdp,   g_Sdp);
    cudaGetSymbolAddress((void**)&Ssa,   g_Ssa);
    cudaGetSymbolAddress((void**)&Sda,   g_Sda);
    cudaGetSymbolAddress((void**)&cs1,   g_cs1);
    cudaGetSymbolAddress((void**)&bsum,  g_bsum);
    cudaGetSymbolAddress((void**)&big1,  g_big1);
    cudaGetSymbolAddress((void**)&x1,    g_x1);
    cudaGetSymbolAddress((void**)&h2,    g_h2);
    cudaGetSymbolAddress((void**)&x2,    g_x2);
    cudaGetSymbolAddress((void**)&es1,   g_es1);
    cudaGetSymbolAddress((void**)&ed1,   g_ed1);
    cudaGetSymbolAddress((void**)&es2,   g_es2);
    cudaGetSymbolAddress((void**)&ed2,   g_ed2);
    cudaGetSymbolAddress((void**)&hseq,  g_hseq);
    cudaGetSymbolAddress((void**)&outp,  g_outp);
    cudaGetSymbolAddress((void**)&outq,  g_outq);

    cudaFuncSetAttribute(tgemm, cudaFuncAttributeMaxDynamicSharedMemorySize, TG_SMEM);
    cudaFuncSetAttribute(tgemm_pre, cudaFuncAttributeMaxDynamicSharedMemorySize, TG_SMEM);

    // --- dependency-free launches first ---
    rowdot_kernel<<<(NP*32 + 255)/256, 256>>>(emb_p, W_out + 512, outp, NP);   // 1
    rowdot_kernel<<<(NQ*32 + 255)/256, 256>>>(emb_q, W_out + 256, outq, NQ);   // 2
    tgemm<<<tg(NP, 1024), 256, TG_SMEM>>>(emb_p, 256, W_ih,       1024, Pih_p, 1024, NP, 1024, 256, 0); // 3
    tgemm<<<tg(NQ, 1024), 256, TG_SMEM>>>(emb_q, 256, W_ih + 256, 1024, Pih_q, 1024, NQ, 1024, 256, 0); // 4
    tgemm<<<tg(2,  1024), 256, TG_SMEM>>>(emb_r, 256, W_ih + 512, 1024, Pih_r, 1024, 2,  1024, 256, 0); // 5
    csr_build<<<1, 512>>>(dst, E);                                             // 6

    // --- weight preprocessing (small) ---
    transpose_k<<<(1024*256)/256, 256>>>(W_hh, WhhT, 1024, 256);
    transpose_k<<<(256*1024)/256, 256>>>(W_g1, Wg1T, 256, 1024);
    transpose_k<<<(512*256)/256,  256>>>(W_affcat, WaT, 512, 256);
    transpose_k<<<(1024*256)/256, 256>>>(W_g2, Wg2T, 1024, 256);

    sgemm_t<<<dim3(8, 4), 256>>>(Wg1T, WaT, WcT, 1024, 256, 512, 0);
    vecmat_k<<<4, 256>>>(b_affcat, W_g1, c1, 256, 1024);
    bsum_k<<<1, 1024>>>(b_ih, b_hh, bsum);

    // --- remaining per-table pre-projections (tf32 tensor cores) ---
    tgemm<<<tg(NP, 1024), 256, TG_SMEM>>>(emb_p,   256, WcT,       512, Pp1, 1024, NP, 1024, 256, 0);
    tgemm<<<tg(NA, 1024), 256, TG_SMEM>>>(emb_aff, 256, WcT + 256, 512, Pa1, 1024, NA, 1024, 256, 0);

    // per-table attention score tables
    score_tab<<<NP, 256>>>(Pp1, a_src1, a_dst1, Ssp, Sdp);
    score_tab<<<NA, 256>>>(Pa1, a_src1, a_dst1, Ssa, Sda);
    cvec_k<<<1, 512>>>(c1, a_src1, a_dst1, cs1);

    // --- GAT layer 1: logits + fused aggregation straight from tables ---
    scores_gather<<<(cBN*8 + 255)/256, 256>>>(p, aff, Ssp, Ssa, Sdp, Sda, cs1, es1, ed1);
    gat1_agg_fused<<<(cBN*32 + 255)/256, 256>>>(p, aff, es1, ed1, src, Pp1, Pa1, c1, b_g1, x1);

    // --- GAT layer 2 ---
    tgemm<<<tg(cBN, 256), 256, TG_SMEM>>>(x1, 1024, Wg2T, 1024, h2, 256, cBN, 256, 1024, 0);
    scores_kernel<<<(cBN*32)/256, 256>>>(h2, a_src2, a_dst2, es2, ed2, 1, 256);
    gat_agg<<<(cBN*32)/256, 256>>>(h2, es2, ed2, src, b_g2, x2, 1, 256, 0);

    // --- LSTM input: GEMM with fused gather-epilogue ---
    tgemm_pre<<<tg(cBN, 1024), 256, TG_SMEM>>>(x2, 256, W_ih + 768, 1024, big1, 1024,
                                               cBN, 1024, 256,
                                               p, q, r, Pih_p, Pih_q, Pih_r, bsum);

    // --- LSTM recurrence (v4: conflict-free smem, broadcast reads) ---
    lstm_cluster<<<128, 512>>>(big1, WhhT, hseq);

    // --- output head ---
    out_kernel<<<(cBN*32)/256, 256>>>(q_next, p_next, W_out, b_out, hseq, outp, outq,
                                      (float*)d_out);
}